// round 6
// baseline (speedup 1.0000x reference)
#include <cuda_runtime.h>
#include <cuda_bf16.h>
#include <stdint.h>

#define N_NODES 50000
#define N_EDGES 800000
#define DIM 128
#define VDIM 32            // DIM/4 float4 per row
#define LEAKY 0.01f
#define LN_EPS 1e-5f

#define SCAN_BLK 256
#define N_SBLK ((N_NODES + SCAN_BLK - 1) / SCAN_BLK)   // 196

// ---------------- scratch (device globals; allocation is forbidden) ----------------
__device__ int    g_deg_in[N_NODES];
__device__ int    g_deg_out[N_NODES];
__device__ float  g_norm_in[N_NODES];
__device__ float  g_norm_out[N_NODES];
__device__ int    g_row_start[N_NODES + 1];
__device__ int    g_fill[N_NODES];
__device__ int    g_col[N_EDGES];
__device__ int    g_bsum[N_SBLK];

__device__ float4 g_x[(size_t)N_NODES * VDIM];     // post LN+leaky features (layer 1)
__device__ float2 g_proj[N_NODES];                 // layer-3 projected features

__device__ __forceinline__ int clamp_idx(int v) {
    v = v < 0 ? 0 : v;
    return v >= N_NODES ? N_NODES - 1 : v;
}

// ---------------- setup ----------------
__global__ void zero_deg_kernel() {
    int i = blockIdx.x * blockDim.x + threadIdx.x;
    if (i < N_NODES) { g_deg_in[i] = 0; g_deg_out[i] = 0; }
}

__global__ void count_deg_kernel(const int* __restrict__ src,
                                 const int* __restrict__ dst) {
    int e = blockIdx.x * blockDim.x + threadIdx.x;
    if (e >= N_EDGES) return;
    atomicAdd(&g_deg_out[clamp_idx(src[e])], 1);
    atomicAdd(&g_deg_in[clamp_idx(dst[e])], 1);
}

// phase A: per-block sums of deg_in
__global__ __launch_bounds__(SCAN_BLK)
void scan_bsum_kernel() {
    int i = blockIdx.x * SCAN_BLK + threadIdx.x;
    int v = (i < N_NODES) ? g_deg_in[i] : 0;
#pragma unroll
    for (int o = 16; o; o >>= 1) v += __shfl_xor_sync(0xffffffffu, v, o);
    __shared__ int wsum[SCAN_BLK / 32];
    if ((threadIdx.x & 31) == 0) wsum[threadIdx.x >> 5] = v;
    __syncthreads();
    if (threadIdx.x == 0) {
        int s = 0;
#pragma unroll
        for (int w = 0; w < SCAN_BLK / 32; w++) s += wsum[w];
        g_bsum[blockIdx.x] = s;
    }
}

// phase B: one-block exclusive scan of the 196 partials
__global__ __launch_bounds__(256)
void scan_partials_kernel() {
    __shared__ int sh[256];
    int tid = threadIdx.x;
    int v = (tid < N_SBLK) ? g_bsum[tid] : 0;
    sh[tid] = v;
    __syncthreads();
#pragma unroll
    for (int off = 1; off < 256; off <<= 1) {
        int t = (tid >= off) ? sh[tid - off] : 0;
        __syncthreads();
        sh[tid] += t;
        __syncthreads();
    }
    if (tid < N_SBLK) g_bsum[tid] = sh[tid] - v;          // exclusive prefix
    if (tid == 255) g_row_start[N_NODES] = sh[255];       // total edge count
}

// phase C: per-block rescan + global offset; also fill pointers and degree norms
__global__ __launch_bounds__(SCAN_BLK)
void scan_final_kernel() {
    int tid = threadIdx.x;
    int i = blockIdx.x * SCAN_BLK + tid;
    int lane = tid & 31, wid = tid >> 5;
    int v = (i < N_NODES) ? g_deg_in[i] : 0;
    int incl = v;
#pragma unroll
    for (int o = 1; o < 32; o <<= 1) {
        int t = __shfl_up_sync(0xffffffffu, incl, o);
        if (lane >= o) incl += t;
    }
    __shared__ int wsum[SCAN_BLK / 32];
    __shared__ int woff[SCAN_BLK / 32];
    if (lane == 31) wsum[wid] = incl;
    __syncthreads();
    if (tid == 0) {
        int s = 0;
#pragma unroll
        for (int w = 0; w < SCAN_BLK / 32; w++) { woff[w] = s; s += wsum[w]; }
    }
    __syncthreads();
    if (i < N_NODES) {
        int excl = incl - v + woff[wid] + g_bsum[blockIdx.x];
        g_row_start[i] = excl;
        g_fill[i] = excl;
        g_norm_out[i] = rsqrtf(fmaxf((float)g_deg_out[i], 1.0f));
        g_norm_in[i]  = rsqrtf(fmaxf((float)v, 1.0f));
    }
}

__global__ void fill_csr_kernel(const int* __restrict__ src,
                                const int* __restrict__ dst) {
    int e = blockIdx.x * blockDim.x + threadIdx.x;
    if (e >= N_EDGES) return;
    int d = clamp_idx(dst[e]);
    int pos = atomicAdd(&g_fill[d], 1);
    g_col[pos] = clamp_idx(src[e]);
}

// ---------------- fused: gather-aggregate -> GEMM -> bias+LN+leaky (+ W3 proj) ----------
// MODE 0: input = feat param, output -> g_x
// MODE 1: input = g_x,        output -> g_proj (projected onto W3 with norm_out)
#define GTM 64
#define GTK 16
template <int MODE>
__global__ __launch_bounds__(256)
void fused_layer_kernel(const float* __restrict__ feat,
                        const float* __restrict__ W, const float* __restrict__ b,
                        const float* __restrict__ g, const float* __restrict__ be,
                        const float* __restrict__ W3) {
    __shared__ float As[GTM][DIM];        // 32 KB: aggregated A tile
    __shared__ float Bs[GTK][DIM + 4];    // 8.25 KB: W K-chunk
    int tid = threadIdx.x;
    int rowBase = blockIdx.x * GTM;
    int lane = tid & 31, wid = tid >> 5;

    // ---- stage 1: gather-aggregate 8 nodes per warp into As ----
#pragma unroll
    for (int n8 = 0; n8 < 8; n8++) {
        int r = wid * 8 + n8;             // 0..63
        int node = rowBase + r;
        float ax = 0.f, ay = 0.f, az = 0.f, aw = 0.f;
        if (node < N_NODES) {
            int beg = g_row_start[node];
            int end = g_row_start[node + 1];
#pragma unroll 2
            for (int e = beg; e < end; e++) {
                int c = g_col[e];
                float w = g_norm_out[c];
                float4 v;
                if (MODE == 1) v = g_x[(size_t)c * VDIM + lane];
                else           v = ((const float4*)(feat + (size_t)c * DIM))[lane];
                ax = fmaf(w, v.x, ax);
                ay = fmaf(w, v.y, ay);
                az = fmaf(w, v.z, az);
                aw = fmaf(w, v.w, aw);
            }
            float ni = g_norm_in[node];
            ax *= ni; ay *= ni; az *= ni; aw *= ni;
        }
        float4 o = { ax, ay, az, aw };
        *(float4*)&As[r][lane * 4] = o;
    }
    __syncthreads();

    // ---- stage 2: register-tiled GEMM from SMEM A, W streamed in K-chunks ----
    int tx = tid & 15;   // 16 col-groups of 8
    int ty = tid >> 4;   // 16 row-groups of 4
    float acc[4][8];
#pragma unroll
    for (int i = 0; i < 4; i++)
#pragma unroll
        for (int j = 0; j < 8; j++) acc[i][j] = 0.f;

    for (int kk = 0; kk < DIM; kk += GTK) {
#pragma unroll
        for (int i = 0; i < 8; i++) {     // 16x128 W chunk: 2048 = 8*256
            int l = tid + i * 256;
            int r = l >> 7, c = l & 127;
            Bs[r][c] = W[(size_t)(kk + r) * DIM + c];
        }
        __syncthreads();
#pragma unroll
        for (int k = 0; k < GTK; k++) {
            float av[4], bv[8];
#pragma unroll
            for (int i = 0; i < 4; i++) av[i] = As[ty * 4 + i][kk + k];
#pragma unroll
            for (int j = 0; j < 8; j++) bv[j] = Bs[k][tx * 8 + j];
#pragma unroll
            for (int i = 0; i < 4; i++)
#pragma unroll
                for (int j = 0; j < 8; j++) acc[i][j] = fmaf(av[i], bv[j], acc[i][j]);
        }
        __syncthreads();
    }

    // ---- epilogue: bias + LayerNorm + leaky (+ optional W3 projection) ----
    int col = tx * 8;
    float bias[8], gg[8], bb[8];
#pragma unroll
    for (int j = 0; j < 8; j++) { bias[j] = b[col + j]; gg[j] = g[col + j]; bb[j] = be[col + j]; }

#pragma unroll
    for (int i = 0; i < 4; i++) {
        int gr = rowBase + ty * 4 + i;
#pragma unroll
        for (int j = 0; j < 8; j++) acc[i][j] += bias[j];
        float s = 0.f;
#pragma unroll
        for (int j = 0; j < 8; j++) s += acc[i][j];
#pragma unroll
        for (int o = 8; o; o >>= 1) s += __shfl_xor_sync(0xffffffffu, s, o);
        float mu = s * (1.f / DIM);
        float q = 0.f;
#pragma unroll
        for (int j = 0; j < 8; j++) { float d = acc[i][j] - mu; q += d * d; }
#pragma unroll
        for (int o = 8; o; o >>= 1) q += __shfl_xor_sync(0xffffffffu, q, o);
        float rstd = rsqrtf(q * (1.f / DIM) + LN_EPS);
        float val[8];
#pragma unroll
        for (int j = 0; j < 8; j++) {
            float t = (acc[i][j] - mu) * rstd * gg[j] + bb[j];
            val[j] = t > 0.f ? t : LEAKY * t;
        }
        if (MODE == 0) {
            if (gr < N_NODES) {
                float4 o0 = { val[0], val[1], val[2], val[3] };
                float4 o1 = { val[4], val[5], val[6], val[7] };
                g_x[(size_t)gr * VDIM + (col >> 2)]     = o0;
                g_x[(size_t)gr * VDIM + (col >> 2) + 1] = o1;
            }
        } else {
            float s0 = 0.f, s1 = 0.f;
#pragma unroll
            for (int j = 0; j < 8; j++) {
                s0 = fmaf(val[j], W3[(col + j) * 2 + 0], s0);
                s1 = fmaf(val[j], W3[(col + j) * 2 + 1], s1);
            }
#pragma unroll
            for (int o = 8; o; o >>= 1) {
                s0 += __shfl_xor_sync(0xffffffffu, s0, o);
                s1 += __shfl_xor_sync(0xffffffffu, s1, o);
            }
            if (tx == 0 && gr < N_NODES) {
                float no = g_norm_out[gr];
                float2 p = { no * s0, no * s1 };
                g_proj[gr] = p;
            }
        }
    }
}

// ---------------- final aggregation over 2-dim projected features ----------------
__global__ void agg2_kernel(const float* __restrict__ b3, float* __restrict__ out) {
    int node = blockIdx.x * blockDim.x + threadIdx.x;
    if (node >= N_NODES) return;
    int beg = g_row_start[node];
    int end = g_row_start[node + 1];
    float a0 = 0.f, a1 = 0.f;
    for (int e = beg; e < end; e++) {
        float2 p = g_proj[g_col[e]];
        a0 += p.x;
        a1 += p.y;
    }
    float ni = g_norm_in[node];
    out[node * 2 + 0] = ni * a0 + b3[0];
    out[node * 2 + 1] = ni * a1 + b3[1];
}

// ---------------- launch: pure kernel launches, no runtime API ----------------
extern "C" void kernel_launch(void* const* d_in, const int* in_sizes, int n_in,
                              void* d_out, int out_size) {
    const float* feat = (const float*)d_in[0];
    const int*   src  = (const int*)d_in[1];   // int32 (JAX x64 disabled)
    const int*   dst  = (const int*)d_in[2];
    const float* W1  = (const float*)d_in[3];
    const float* b1  = (const float*)d_in[4];
    const float* W2  = (const float*)d_in[5];
    const float* b2  = (const float*)d_in[6];
    const float* W3  = (const float*)d_in[7];
    const float* b3  = (const float*)d_in[8];
    const float* g1  = (const float*)d_in[9];
    const float* be1 = (const float*)d_in[10];
    const float* g2  = (const float*)d_in[11];
    const float* be2 = (const float*)d_in[12];
    float* out = (float*)d_out;

    const int NB_N = (N_NODES + 255) / 256;
    const int NB_E = (N_EDGES + 255) / 256;
    const int NB_G = (N_NODES + GTM - 1) / GTM;

    // graph structure
    zero_deg_kernel<<<NB_N, 256>>>();
    count_deg_kernel<<<NB_E, 256>>>(src, dst);
    scan_bsum_kernel<<<N_SBLK, SCAN_BLK>>>();
    scan_partials_kernel<<<1, 256>>>();
    scan_final_kernel<<<N_SBLK, SCAN_BLK>>>();   // also norms + fill ptrs
    fill_csr_kernel<<<NB_E, 256>>>(src, dst);

    // layer 1: fused gather+gemm+bias+LN+leaky -> g_x
    fused_layer_kernel<0><<<NB_G, 256>>>(feat, W1, b1, g1, be1, nullptr);

    // layer 2: fused gather+gemm+bias+LN+leaky+W3 projection -> g_proj
    fused_layer_kernel<1><<<NB_G, 256>>>(feat, W2, b2, g2, be2, W3);

    // layer 3 aggregation over 2-dim projections
    agg2_kernel<<<NB_N, 256>>>(b3, out);
}

// round 7
// speedup vs baseline: 1.2305x; 1.2305x over previous
#include <cuda_runtime.h>
#include <cuda_bf16.h>
#include <stdint.h>

#define N_NODES 50000
#define N_EDGES 800000
#define DIM 128
#define VDIM 32            // DIM/4 float4 per row
#define LEAKY 0.01f
#define LN_EPS 1e-5f

#define SCAN_BLK 256
#define N_SBLK ((N_NODES + SCAN_BLK - 1) / SCAN_BLK)   // 196

// ---------------- scratch (device globals; allocation is forbidden) ----------------
__device__ int    g_deg_in[N_NODES];
__device__ int    g_deg_out[N_NODES];
__device__ float  g_norm_in[N_NODES];
__device__ float  g_norm_out[N_NODES];
__device__ int    g_row_start[N_NODES + 1];
__device__ int    g_fill[N_NODES];
__device__ int    g_col[N_EDGES];
__device__ int    g_bsum[N_SBLK];

__device__ float4 g_agg[(size_t)N_NODES * VDIM];   // aggregation output
__device__ float4 g_x[(size_t)N_NODES * VDIM];     // post LN+leaky features (layer 1)
__device__ float2 g_proj[N_NODES];                 // layer-3 projected features

__device__ __forceinline__ int clamp_idx(int v) {
    v = v < 0 ? 0 : v;
    return v >= N_NODES ? N_NODES - 1 : v;
}

// ---------------- setup ----------------
__global__ void zero_deg_kernel() {
    int i = blockIdx.x * blockDim.x + threadIdx.x;
    if (i < N_NODES) { g_deg_in[i] = 0; g_deg_out[i] = 0; }
}

// 4 edges per thread via int4
__global__ void count_deg_kernel(const int4* __restrict__ src4,
                                 const int4* __restrict__ dst4) {
    int t = blockIdx.x * blockDim.x + threadIdx.x;
    if (t >= N_EDGES / 4) return;
    int4 s = src4[t];
    int4 d = dst4[t];
    atomicAdd(&g_deg_out[clamp_idx(s.x)], 1);
    atomicAdd(&g_deg_out[clamp_idx(s.y)], 1);
    atomicAdd(&g_deg_out[clamp_idx(s.z)], 1);
    atomicAdd(&g_deg_out[clamp_idx(s.w)], 1);
    atomicAdd(&g_deg_in[clamp_idx(d.x)], 1);
    atomicAdd(&g_deg_in[clamp_idx(d.y)], 1);
    atomicAdd(&g_deg_in[clamp_idx(d.z)], 1);
    atomicAdd(&g_deg_in[clamp_idx(d.w)], 1);
}

// phase A: per-block sums of deg_in
__global__ __launch_bounds__(SCAN_BLK)
void scan_bsum_kernel() {
    int i = blockIdx.x * SCAN_BLK + threadIdx.x;
    int v = (i < N_NODES) ? g_deg_in[i] : 0;
#pragma unroll
    for (int o = 16; o; o >>= 1) v += __shfl_xor_sync(0xffffffffu, v, o);
    __shared__ int wsum[SCAN_BLK / 32];
    if ((threadIdx.x & 31) == 0) wsum[threadIdx.x >> 5] = v;
    __syncthreads();
    if (threadIdx.x == 0) {
        int s = 0;
#pragma unroll
        for (int w = 0; w < SCAN_BLK / 32; w++) s += wsum[w];
        g_bsum[blockIdx.x] = s;
    }
}

// phase B: one-block exclusive scan of the 196 partials
__global__ __launch_bounds__(256)
void scan_partials_kernel() {
    __shared__ int sh[256];
    int tid = threadIdx.x;
    int v = (tid < N_SBLK) ? g_bsum[tid] : 0;
    sh[tid] = v;
    __syncthreads();
#pragma unroll
    for (int off = 1; off < 256; off <<= 1) {
        int t = (tid >= off) ? sh[tid - off] : 0;
        __syncthreads();
        sh[tid] += t;
        __syncthreads();
    }
    if (tid < N_SBLK) g_bsum[tid] = sh[tid] - v;          // exclusive prefix
    if (tid == 255) g_row_start[N_NODES] = sh[255];       // total edge count
}

// phase C: per-block rescan + global offset; also fill pointers and degree norms
__global__ __launch_bounds__(SCAN_BLK)
void scan_final_kernel() {
    int tid = threadIdx.x;
    int i = blockIdx.x * SCAN_BLK + tid;
    int lane = tid & 31, wid = tid >> 5;
    int v = (i < N_NODES) ? g_deg_in[i] : 0;
    int incl = v;
#pragma unroll
    for (int o = 1; o < 32; o <<= 1) {
        int t = __shfl_up_sync(0xffffffffu, incl, o);
        if (lane >= o) incl += t;
    }
    __shared__ int wsum[SCAN_BLK / 32];
    __shared__ int woff[SCAN_BLK / 32];
    if (lane == 31) wsum[wid] = incl;
    __syncthreads();
    if (tid == 0) {
        int s = 0;
#pragma unroll
        for (int w = 0; w < SCAN_BLK / 32; w++) { woff[w] = s; s += wsum[w]; }
    }
    __syncthreads();
    if (i < N_NODES) {
        int excl = incl - v + woff[wid] + g_bsum[blockIdx.x];
        g_row_start[i] = excl;
        g_fill[i] = excl;
        g_norm_out[i] = rsqrtf(fmaxf((float)g_deg_out[i], 1.0f));
        g_norm_in[i]  = rsqrtf(fmaxf((float)v, 1.0f));
    }
}

// 4 edges per thread via int4
__global__ void fill_csr_kernel(const int4* __restrict__ src4,
                                const int4* __restrict__ dst4) {
    int t = blockIdx.x * blockDim.x + threadIdx.x;
    if (t >= N_EDGES / 4) return;
    int4 s = src4[t];
    int4 d = dst4[t];
    int p;
    p = atomicAdd(&g_fill[clamp_idx(d.x)], 1); g_col[p] = clamp_idx(s.x);
    p = atomicAdd(&g_fill[clamp_idx(d.y)], 1); g_col[p] = clamp_idx(s.y);
    p = atomicAdd(&g_fill[clamp_idx(d.z)], 1); g_col[p] = clamp_idx(s.z);
    p = atomicAdd(&g_fill[clamp_idx(d.w)], 1); g_col[p] = clamp_idx(s.w);
}

// ---------------- aggregation: warp per node, 128 feats as float4/lane ----------------
template <bool USE_GX>
__global__ __launch_bounds__(256)
void agg128_kernel(const float* __restrict__ feat) {
    int node = blockIdx.x * (blockDim.x >> 5) + (threadIdx.x >> 5);
    if (node >= N_NODES) return;
    int lane = threadIdx.x & 31;
    int beg = g_row_start[node];
    int end = g_row_start[node + 1];
    float ax = 0.f, ay = 0.f, az = 0.f, aw = 0.f;
#pragma unroll 4
    for (int e = beg; e < end; e++) {
        int c = g_col[e];
        float w = g_norm_out[c];
        float4 v;
        if (USE_GX) v = g_x[(size_t)c * VDIM + lane];
        else        v = ((const float4*)(feat + (size_t)c * DIM))[lane];
        ax = fmaf(w, v.x, ax);
        ay = fmaf(w, v.y, ay);
        az = fmaf(w, v.z, az);
        aw = fmaf(w, v.w, aw);
    }
    float ni = g_norm_in[node];
    float4 o = { ax * ni, ay * ni, az * ni, aw * ni };
    g_agg[(size_t)node * VDIM + lane] = o;
}

// ---------------- fused GEMM + bias + LayerNorm + LeakyReLU (+ optional W3 projection) ----
// 128-row tile, 8x8 per thread. MODE 0: -> g_x. MODE 1: -> g_proj (W3 projection).
#define GTM 128
#define GTK 32
template <int MODE>
__global__ __launch_bounds__(256)
void gemm_ln_kernel(const float* __restrict__ W, const float* __restrict__ b,
                    const float* __restrict__ g, const float* __restrict__ be,
                    const float* __restrict__ W3) {
    __shared__ float As[GTM][GTK + 1];     // 16.5 KB
    __shared__ float Bs[GTK][DIM + 4];     // 16.5 KB
    int tid = threadIdx.x;
    int rowBase = blockIdx.x * GTM;
    int tx = tid & 15;   // 16 col-groups of 8
    int ty = tid >> 4;   // 16 row-groups of 8
    float acc[8][8];
#pragma unroll
    for (int i = 0; i < 8; i++)
#pragma unroll
        for (int j = 0; j < 8; j++) acc[i][j] = 0.f;

    const float* Af = (const float*)g_agg;
    for (int kk = 0; kk < DIM; kk += GTK) {
#pragma unroll
        for (int i = 0; i < 16; i++) {       // 128x32 A tile: 4096 = 16*256
            int l = tid + i * 256;
            int r = l >> 5, c = l & 31;
            int gr = rowBase + r;
            As[r][c] = (gr < N_NODES) ? Af[(size_t)gr * DIM + kk + c] : 0.f;
        }
#pragma unroll
        for (int i = 0; i < 16; i++) {       // 32x128 W tile: 4096 = 16*256
            int l = tid + i * 256;
            int r = l >> 7, c = l & 127;
            Bs[r][c] = W[(size_t)(kk + r) * DIM + c];
        }
        __syncthreads();
#pragma unroll
        for (int k = 0; k < GTK; k++) {
            float av[8], bv[8];
#pragma unroll
            for (int i = 0; i < 8; i++) av[i] = As[ty * 8 + i][k];
#pragma unroll
            for (int j = 0; j < 8; j++) bv[j] = Bs[k][tx * 8 + j];
#pragma unroll
            for (int i = 0; i < 8; i++)
#pragma unroll
                for (int j = 0; j < 8; j++) acc[i][j] = fmaf(av[i], bv[j], acc[i][j]);
        }
        __syncthreads();
    }

    // epilogue: bias + LayerNorm + leaky (+ optional projection), all in registers
    int col = tx * 8;
    float bias[8], gg[8], bb[8];
#pragma unroll
    for (int j = 0; j < 8; j++) { bias[j] = b[col + j]; gg[j] = g[col + j]; bb[j] = be[col + j]; }

#pragma unroll
    for (int i = 0; i < 8; i++) {
        int gr = rowBase + ty * 8 + i;
#pragma unroll
        for (int j = 0; j < 8; j++) acc[i][j] += bias[j];
        // 16 threads (same row, consecutive lanes within half-warp) reduce over 128 cols
        float s = 0.f;
#pragma unroll
        for (int j = 0; j < 8; j++) s += acc[i][j];
#pragma unroll
        for (int o = 8; o; o >>= 1) s += __shfl_xor_sync(0xffffffffu, s, o);
        float mu = s * (1.f / DIM);
        float q = 0.f;
#pragma unroll
        for (int j = 0; j < 8; j++) { float d = acc[i][j] - mu; q += d * d; }
#pragma unroll
        for (int o = 8; o; o >>= 1) q += __shfl_xor_sync(0xffffffffu, q, o);
        float rstd = rsqrtf(q * (1.f / DIM) + LN_EPS);
        float val[8];
#pragma unroll
        for (int j = 0; j < 8; j++) {
            float t = (acc[i][j] - mu) * rstd * gg[j] + bb[j];
            val[j] = t > 0.f ? t : LEAKY * t;
        }
        if (MODE == 0) {
            if (gr < N_NODES) {
                float4 o0 = { val[0], val[1], val[2], val[3] };
                float4 o1 = { val[4], val[5], val[6], val[7] };
                g_x[(size_t)gr * VDIM + (col >> 2)]     = o0;
                g_x[(size_t)gr * VDIM + (col >> 2) + 1] = o1;
            }
        } else {
            float s0 = 0.f, s1 = 0.f;
#pragma unroll
            for (int j = 0; j < 8; j++) {
                s0 = fmaf(val[j], W3[(col + j) * 2 + 0], s0);
                s1 = fmaf(val[j], W3[(col + j) * 2 + 1], s1);
            }
#pragma unroll
            for (int o = 8; o; o >>= 1) {
                s0 += __shfl_xor_sync(0xffffffffu, s0, o);
                s1 += __shfl_xor_sync(0xffffffffu, s1, o);
            }
            if (tx == 0 && gr < N_NODES) {
                float no = g_norm_out[gr];
                float2 p = { no * s0, no * s1 };
                g_proj[gr] = p;
            }
        }
    }
}

// ---------------- final aggregation over 2-dim projected features ----------------
__global__ void agg2_kernel(const float* __restrict__ b3, float* __restrict__ out) {
    int node = blockIdx.x * blockDim.x + threadIdx.x;
    if (node >= N_NODES) return;
    int beg = g_row_start[node];
    int end = g_row_start[node + 1];
    float a0 = 0.f, a1 = 0.f;
    for (int e = beg; e < end; e++) {
        float2 p = g_proj[g_col[e]];
        a0 += p.x;
        a1 += p.y;
    }
    float ni = g_norm_in[node];
    out[node * 2 + 0] = ni * a0 + b3[0];
    out[node * 2 + 1] = ni * a1 + b3[1];
}

// ---------------- launch: pure kernel launches, no runtime API ----------------
extern "C" void kernel_launch(void* const* d_in, const int* in_sizes, int n_in,
                              void* d_out, int out_size) {
    const float* feat = (const float*)d_in[0];
    const int*   src  = (const int*)d_in[1];   // int32 (JAX x64 disabled)
    const int*   dst  = (const int*)d_in[2];
    const float* W1  = (const float*)d_in[3];
    const float* b1  = (const float*)d_in[4];
    const float* W2  = (const float*)d_in[5];
    const float* b2  = (const float*)d_in[6];
    const float* W3  = (const float*)d_in[7];
    const float* b3  = (const float*)d_in[8];
    const float* g1  = (const float*)d_in[9];
    const float* be1 = (const float*)d_in[10];
    const float* g2  = (const float*)d_in[11];
    const float* be2 = (const float*)d_in[12];
    float* out = (float*)d_out;

    const int NB_N  = (N_NODES + 255) / 256;
    const int NB_E4 = (N_EDGES / 4 + 255) / 256;
    const int NB_W  = (N_NODES + 7) / 8;     // warp-per-node, 8 warps/block
    const int NB_G  = (N_NODES + GTM - 1) / GTM;

    // graph structure
    zero_deg_kernel<<<NB_N, 256>>>();
    count_deg_kernel<<<NB_E4, 256>>>((const int4*)src, (const int4*)dst);
    scan_bsum_kernel<<<N_SBLK, SCAN_BLK>>>();
    scan_partials_kernel<<<1, 256>>>();
    scan_final_kernel<<<N_SBLK, SCAN_BLK>>>();   // also norms + fill ptrs
    fill_csr_kernel<<<NB_E4, 256>>>((const int4*)src, (const int4*)dst);

    // layer 1: agg -> fused gemm+bias+LN+leaky -> g_x
    agg128_kernel<false><<<NB_W, 256>>>(feat);
    gemm_ln_kernel<0><<<NB_G, 256>>>(W1, b1, g1, be1, nullptr);

    // layer 2: agg -> fused gemm+bias+LN+leaky+W3 projection -> g_proj
    agg128_kernel<true><<<NB_W, 256>>>(feat);
    gemm_ln_kernel<1><<<NB_G, 256>>>(W2, b2, g2, be2, W3);

    // layer 3 aggregation over 2-dim projections
    agg2_kernel<<<NB_N, 256>>>(b3, out);
}

// round 9
// speedup vs baseline: 1.2654x; 1.0284x over previous
#include <cuda_runtime.h>
#include <cuda_bf16.h>
#include <stdint.h>

#define N_NODES 50000
#define N_EDGES 800000
#define DIM 128
#define VDIM 32            // DIM/4 float4 per row
#define LEAKY 0.01f
#define LN_EPS 1e-5f

#define SCAN_BLK 256
#define N_SBLK ((N_NODES + SCAN_BLK - 1) / SCAN_BLK)   // 196

// ---------------- scratch (device globals; allocation is forbidden) ----------------
__device__ int    g_deg_in[N_NODES];
__device__ int    g_deg_out[N_NODES];
__device__ float  g_norm_in[N_NODES];
__device__ float  g_norm_out[N_NODES];
__device__ int    g_row_start[N_NODES + 1];
__device__ int    g_fill[N_NODES];
__device__ int    g_col[N_EDGES];
__device__ int    g_bsum[N_SBLK];

__device__ float4 g_agg[(size_t)N_NODES * VDIM];   // aggregation output (fp32)
__device__ float4 g_x[(size_t)N_NODES * VDIM];     // post LN+leaky features (fp32)
__device__ float2 g_proj[N_NODES];                 // layer-3 projected features

__device__ __forceinline__ int clamp_idx(int v) {
    v = v < 0 ? 0 : v;
    return v >= N_NODES ? N_NODES - 1 : v;
}

// ---------------- tf32 mma helpers (base PTX, plain sm_100-safe) ----------------
__device__ __forceinline__ uint32_t cvt_tf32(float f) {
    uint32_t r;
    asm("cvt.rna.tf32.f32 %0, %1;" : "=r"(r) : "f"(f));
    return r;
}
__device__ __forceinline__ void mma8(float* c, const uint32_t* a, const uint32_t* b) {
    asm volatile(
        "mma.sync.aligned.m16n8k8.row.col.f32.tf32.tf32.f32 "
        "{%0,%1,%2,%3}, {%4,%5,%6,%7}, {%8,%9}, {%0,%1,%2,%3};"
        : "+f"(c[0]), "+f"(c[1]), "+f"(c[2]), "+f"(c[3])
        : "r"(a[0]), "r"(a[1]), "r"(a[2]), "r"(a[3]), "r"(b[0]), "r"(b[1]));
}

// ---------------- setup ----------------
__global__ void zero_deg_kernel() {
    int i = blockIdx.x * blockDim.x + threadIdx.x;
    if (i < N_NODES) { g_deg_in[i] = 0; g_deg_out[i] = 0; }
}

__global__ void count_deg_kernel(const int4* __restrict__ src4,
                                 const int4* __restrict__ dst4) {
    int t = blockIdx.x * blockDim.x + threadIdx.x;
    if (t >= N_EDGES / 4) return;
    int4 s = src4[t];
    int4 d = dst4[t];
    atomicAdd(&g_deg_out[clamp_idx(s.x)], 1);
    atomicAdd(&g_deg_out[clamp_idx(s.y)], 1);
    atomicAdd(&g_deg_out[clamp_idx(s.z)], 1);
    atomicAdd(&g_deg_out[clamp_idx(s.w)], 1);
    atomicAdd(&g_deg_in[clamp_idx(d.x)], 1);
    atomicAdd(&g_deg_in[clamp_idx(d.y)], 1);
    atomicAdd(&g_deg_in[clamp_idx(d.z)], 1);
    atomicAdd(&g_deg_in[clamp_idx(d.w)], 1);
}

__global__ __launch_bounds__(SCAN_BLK)
void scan_bsum_kernel() {
    int i = blockIdx.x * SCAN_BLK + threadIdx.x;
    int v = (i < N_NODES) ? g_deg_in[i] : 0;
#pragma unroll
    for (int o = 16; o; o >>= 1) v += __shfl_xor_sync(0xffffffffu, v, o);
    __shared__ int wsum[SCAN_BLK / 32];
    if ((threadIdx.x & 31) == 0) wsum[threadIdx.x >> 5] = v;
    __syncthreads();
    if (threadIdx.x == 0) {
        int s = 0;
#pragma unroll
        for (int w = 0; w < SCAN_BLK / 32; w++) s += wsum[w];
        g_bsum[blockIdx.x] = s;
    }
}

__global__ __launch_bounds__(256)
void scan_partials_kernel() {
    __shared__ int sh[256];
    int tid = threadIdx.x;
    int v = (tid < N_SBLK) ? g_bsum[tid] : 0;
    sh[tid] = v;
    __syncthreads();
#pragma unroll
    for (int off = 1; off < 256; off <<= 1) {
        int t = (tid >= off) ? sh[tid - off] : 0;
        __syncthreads();
        sh[tid] += t;
        __syncthreads();
    }
    if (tid < N_SBLK) g_bsum[tid] = sh[tid] - v;
    if (tid == 255) g_row_start[N_NODES] = sh[255];
}

__global__ __launch_bounds__(SCAN_BLK)
void scan_final_kernel() {
    int tid = threadIdx.x;
    int i = blockIdx.x * SCAN_BLK + tid;
    int lane = tid & 31, wid = tid >> 5;
    int v = (i < N_NODES) ? g_deg_in[i] : 0;
    int incl = v;
#pragma unroll
    for (int o = 1; o < 32; o <<= 1) {
        int t = __shfl_up_sync(0xffffffffu, incl, o);
        if (lane >= o) incl += t;
    }
    __shared__ int wsum[SCAN_BLK / 32];
    __shared__ int woff[SCAN_BLK / 32];
    if (lane == 31) wsum[wid] = incl;
    __syncthreads();
    if (tid == 0) {
        int s = 0;
#pragma unroll
        for (int w = 0; w < SCAN_BLK / 32; w++) { woff[w] = s; s += wsum[w]; }
    }
    __syncthreads();
    if (i < N_NODES) {
        int excl = incl - v + woff[wid] + g_bsum[blockIdx.x];
        g_row_start[i] = excl;
        g_fill[i] = excl;
        g_norm_out[i] = rsqrtf(fmaxf((float)g_deg_out[i], 1.0f));
        g_norm_in[i]  = rsqrtf(fmaxf((float)v, 1.0f));
    }
}

__global__ void fill_csr_kernel(const int4* __restrict__ src4,
                                const int4* __restrict__ dst4) {
    int t = blockIdx.x * blockDim.x + threadIdx.x;
    if (t >= N_EDGES / 4) return;
    int4 s = src4[t];
    int4 d = dst4[t];
    int p;
    p = atomicAdd(&g_fill[clamp_idx(d.x)], 1); g_col[p] = clamp_idx(s.x);
    p = atomicAdd(&g_fill[clamp_idx(d.y)], 1); g_col[p] = clamp_idx(s.y);
    p = atomicAdd(&g_fill[clamp_idx(d.z)], 1); g_col[p] = clamp_idx(s.z);
    p = atomicAdd(&g_fill[clamp_idx(d.w)], 1); g_col[p] = clamp_idx(s.w);
}

// ---------------- aggregation: warp per node, 128 feats as float4/lane ----------------
template <bool USE_GX>
__global__ __launch_bounds__(256)
void agg128_kernel(const float* __restrict__ feat) {
    int node = blockIdx.x * (blockDim.x >> 5) + (threadIdx.x >> 5);
    if (node >= N_NODES) return;
    int lane = threadIdx.x & 31;
    int beg = g_row_start[node];
    int end = g_row_start[node + 1];
    float ax = 0.f, ay = 0.f, az = 0.f, aw = 0.f;
#pragma unroll 4
    for (int e = beg; e < end; e++) {
        int c = g_col[e];
        float w = g_norm_out[c];
        float4 v;
        if (USE_GX) v = g_x[(size_t)c * VDIM + lane];
        else        v = ((const float4*)(feat + (size_t)c * DIM))[lane];
        ax = fmaf(w, v.x, ax);
        ay = fmaf(w, v.y, ay);
        az = fmaf(w, v.z, az);
        aw = fmaf(w, v.w, aw);
    }
    float ni = g_norm_in[node];
    float4 o = { ax * ni, ay * ni, az * ni, aw * ni };
    g_agg[(size_t)node * VDIM + lane] = o;
}

// ---------------- tf32 mma GEMM + bias + LN + leaky (+ W3 projection) -----------------
// Block tile 128x128, K=128 in 8 chunks of 16. 8 warps: 4 along M (32 rows), 2 along N (64 cols).
// 3-term tf32 split: hi*hi + hi*lo + lo*hi, fp32 accumulate.
// MODE 0 -> g_x. MODE 1 -> g_proj (W3 projection with norm_out).
#define APITCH 20
#define BPITCH 136
template <int MODE>
__global__ __launch_bounds__(256)
void gemm_mma_kernel(const float* __restrict__ W, const float* __restrict__ b,
                     const float* __restrict__ g, const float* __restrict__ be,
                     const float* __restrict__ W3) {
    __shared__ uint32_t As_hi[128][APITCH], As_lo[128][APITCH];   // 20 KB
    __shared__ uint32_t Bs_hi[16][BPITCH],  Bs_lo[16][BPITCH];    // 17 KB
    __shared__ float sh_b[128], sh_g[128], sh_be[128], sh_w3[256];
    __shared__ float sh_s0[128][2], sh_s1[128][2];                // cross-warp partials

    int tid = threadIdx.x;
    int wid = tid >> 5, lane = tid & 31;
    int lg = lane >> 2, lt = lane & 3;
    int warp_m = wid & 3, warp_n = wid >> 2;
    int mbase = warp_m * 32, nbase = warp_n * 64;
    int rowBase = blockIdx.x * 128;

    if (tid < 128) { sh_b[tid] = b[tid]; sh_g[tid] = g[tid]; sh_be[tid] = be[tid]; }
    if (MODE == 1 && tid >= 128) sh_w3[2 * (tid - 128)] = W3[2 * (tid - 128)];
    if (MODE == 1 && tid >= 128) sh_w3[2 * (tid - 128) + 1] = W3[2 * (tid - 128) + 1];

    float acc[2][8][4];
#pragma unroll
    for (int m = 0; m < 2; m++)
#pragma unroll
        for (int n = 0; n < 8; n++)
#pragma unroll
            for (int e = 0; e < 4; e++) acc[m][n][e] = 0.f;

    const float* Af = (const float*)g_agg;

    for (int kc = 0; kc < 8; kc++) {
        // stage A chunk (128 x 16) and W chunk (16 x 128), split into tf32 hi/lo
#pragma unroll
        for (int i = 0; i < 2; i++) {
            int e = tid + i * 256;           // 0..511
            {   // A: row = e>>2 (128), float4 group = e&3 (4 per row)
                int row = e >> 2, c4 = (e & 3) * 4;
                int gr = rowBase + row;
                float4 v = make_float4(0.f, 0.f, 0.f, 0.f);
                if (gr < N_NODES)
                    v = *(const float4*)(Af + (size_t)gr * DIM + kc * 16 + c4);
                uint32_t h0 = cvt_tf32(v.x), h1 = cvt_tf32(v.y), h2 = cvt_tf32(v.z), h3 = cvt_tf32(v.w);
                As_hi[row][c4 + 0] = h0; As_lo[row][c4 + 0] = cvt_tf32(v.x - __uint_as_float(h0));
                As_hi[row][c4 + 1] = h1; As_lo[row][c4 + 1] = cvt_tf32(v.y - __uint_as_float(h1));
                As_hi[row][c4 + 2] = h2; As_lo[row][c4 + 2] = cvt_tf32(v.z - __uint_as_float(h2));
                As_hi[row][c4 + 3] = h3; As_lo[row][c4 + 3] = cvt_tf32(v.w - __uint_as_float(h3));
            }
            {   // W: k = e>>5 (16), float4 group = e&31 (32 per row)
                int k = e >> 5, c4 = (e & 31) * 4;
                float4 v = *(const float4*)(W + (size_t)(kc * 16 + k) * DIM + c4);
                uint32_t h0 = cvt_tf32(v.x), h1 = cvt_tf32(v.y), h2 = cvt_tf32(v.z), h3 = cvt_tf32(v.w);
                Bs_hi[k][c4 + 0] = h0; Bs_lo[k][c4 + 0] = cvt_tf32(v.x - __uint_as_float(h0));
                Bs_hi[k][c4 + 1] = h1; Bs_lo[k][c4 + 1] = cvt_tf32(v.y - __uint_as_float(h1));
                Bs_hi[k][c4 + 2] = h2; Bs_lo[k][c4 + 2] = cvt_tf32(v.z - __uint_as_float(h2));
                Bs_hi[k][c4 + 3] = h3; Bs_lo[k][c4 + 3] = cvt_tf32(v.w - __uint_as_float(h3));
            }
        }
        __syncthreads();

#pragma unroll
        for (int ks = 0; ks < 2; ks++) {
            int kb = ks * 8;
            uint32_t a_hi[2][4], a_lo[2][4];
#pragma unroll
            for (int m = 0; m < 2; m++) {
                int r0 = mbase + m * 16 + lg;
                a_hi[m][0] = As_hi[r0][kb + lt];
                a_hi[m][1] = As_hi[r0 + 8][kb + lt];
                a_hi[m][2] = As_hi[r0][kb + lt + 4];
                a_hi[m][3] = As_hi[r0 + 8][kb + lt + 4];
                a_lo[m][0] = As_lo[r0][kb + lt];
                a_lo[m][1] = As_lo[r0 + 8][kb + lt];
                a_lo[m][2] = As_lo[r0][kb + lt + 4];
                a_lo[m][3] = As_lo[r0 + 8][kb + lt + 4];
            }
            uint32_t b_hi[8][2], b_lo[8][2];
#pragma unroll
            for (int n = 0; n < 8; n++) {
                int c0 = nbase + n * 8 + lg;
                b_hi[n][0] = Bs_hi[kb + lt][c0];
                b_hi[n][1] = Bs_hi[kb + lt + 4][c0];
                b_lo[n][0] = Bs_lo[kb + lt][c0];
                b_lo[n][1] = Bs_lo[kb + lt + 4][c0];
            }
#pragma unroll
            for (int m = 0; m < 2; m++)
#pragma unroll
                for (int n = 0; n < 8; n++) {
                    mma8(acc[m][n], a_hi[m], b_hi[n]);
                    mma8(acc[m][n], a_hi[m], b_lo[n]);
                    mma8(acc[m][n], a_lo[m], b_hi[n]);
                }
        }
        __syncthreads();
    }

    // ---- epilogue: bias, LN stats via shfl + cross-warp SMEM, leaky, output ----
    // thread's rows: m in {0,1}, half h in {0,1}: row = mbase + m*16 + lg + h*8
    // thread's cols per n-tile: nbase + n*8 + 2*lt (+1); e index: h*2 + (col parity)
#pragma unroll
    for (int m = 0; m < 2; m++)
#pragma unroll
        for (int n = 0; n < 8; n++) {
            int col = nbase + n * 8 + 2 * lt;
            acc[m][n][0] += sh_b[col];
            acc[m][n][1] += sh_b[col + 1];
            acc[m][n][2] += sh_b[col];
            acc[m][n][3] += sh_b[col + 1];
        }

    float rs[2][2];
#pragma unroll
    for (int m = 0; m < 2; m++) {
        float s0 = 0.f, s1 = 0.f;
#pragma unroll
        for (int n = 0; n < 8; n++) {
            s0 += acc[m][n][0] + acc[m][n][1];
            s1 += acc[m][n][2] + acc[m][n][3];
        }
        rs[m][0] = s0; rs[m][1] = s1;
    }
#pragma unroll
    for (int o = 1; o <= 2; o <<= 1) {
#pragma unroll
        for (int m = 0; m < 2; m++) {
            rs[m][0] += __shfl_xor_sync(0xffffffffu, rs[m][0], o);
            rs[m][1] += __shfl_xor_sync(0xffffffffu, rs[m][1], o);
        }
    }
    if (lt == 0) {
#pragma unroll
        for (int m = 0; m < 2; m++) {
            sh_s0[mbase + m * 16 + lg][warp_n] = rs[m][0];
            sh_s0[mbase + m * 16 + lg + 8][warp_n] = rs[m][1];
        }
    }
    __syncthreads();

    float mu[2][2];
#pragma unroll
    for (int m = 0; m < 2; m++) {
        int r0 = mbase + m * 16 + lg;
        mu[m][0] = (sh_s0[r0][0] + sh_s0[r0][1]) * (1.f / DIM);
        mu[m][1] = (sh_s0[r0 + 8][0] + sh_s0[r0 + 8][1]) * (1.f / DIM);
    }

    float qs[2][2];
#pragma unroll
    for (int m = 0; m < 2; m++) {
        float q0 = 0.f, q1 = 0.f;
#pragma unroll
        for (int n = 0; n < 8; n++) {
            float d;
            d = acc[m][n][0] - mu[m][0]; q0 += d * d;
            d = acc[m][n][1] - mu[m][0]; q0 += d * d;
            d = acc[m][n][2] - mu[m][1]; q1 += d * d;
            d = acc[m][n][3] - mu[m][1]; q1 += d * d;
        }
        qs[m][0] = q0; qs[m][1] = q1;
    }
#pragma unroll
    for (int o = 1; o <= 2; o <<= 1) {
#pragma unroll
        for (int m = 0; m < 2; m++) {
            qs[m][0] += __shfl_xor_sync(0xffffffffu, qs[m][0], o);
            qs[m][1] += __shfl_xor_sync(0xffffffffu, qs[m][1], o);
        }
    }
    if (lt == 0) {
#pragma unroll
        for (int m = 0; m < 2; m++) {
            sh_s1[mbase + m * 16 + lg][warp_n] = qs[m][0];
            sh_s1[mbase + m * 16 + lg + 8][warp_n] = qs[m][1];
        }
    }
    __syncthreads();

    float rstd[2][2];
#pragma unroll
    for (int m = 0; m < 2; m++) {
        int r0 = mbase + m * 16 + lg;
        rstd[m][0] = rsqrtf((sh_s1[r0][0] + sh_s1[r0][1]) * (1.f / DIM) + LN_EPS);
        rstd[m][1] = rsqrtf((sh_s1[r0 + 8][0] + sh_s1[r0 + 8][1]) * (1.f / DIM) + LN_EPS);
    }

    if (MODE == 0) {
        float* xf = (float*)g_x;
#pragma unroll
        for (int m = 0; m < 2; m++) {
            int r0 = mbase + m * 16 + lg;
#pragma unroll
            for (int h = 0; h < 2; h++) {
                int gr = rowBase + r0 + h * 8;
                if (gr < N_NODES) {
#pragma unroll
                    for (int n = 0; n < 8; n++) {
                        int col = nbase + n * 8 + 2 * lt;
                        float v0 = (acc[m][n][h * 2 + 0] - mu[m][h]) * rstd[m][h] * sh_g[col] + sh_be[col];
                        float v1 = (acc[m][n][h * 2 + 1] - mu[m][h]) * rstd[m][h] * sh_g[col + 1] + sh_be[col + 1];
                        v0 = v0 > 0.f ? v0 : LEAKY * v0;
                        v1 = v1 > 0.f ? v1 : LEAKY * v1;
                        float2 p = { v0, v1 };
                        *(float2*)(xf + (size_t)gr * DIM + col) = p;
                    }
                }
            }
        }
    } else {
        // projection partials, reuse sh_s0/sh_s1 (all reads done; need barrier first)
        __syncthreads();
        float p0[2][2], p1[2][2];
#pragma unroll
        for (int m = 0; m < 2; m++)
#pragma unroll
            for (int h = 0; h < 2; h++) { p0[m][h] = 0.f; p1[m][h] = 0.f; }
#pragma unroll
        for (int m = 0; m < 2; m++)
#pragma unroll
            for (int n = 0; n < 8; n++) {
                int col = nbase + n * 8 + 2 * lt;
#pragma unroll
                for (int h = 0; h < 2; h++) {
                    float v0 = (acc[m][n][h * 2 + 0] - mu[m][h]) * rstd[m][h] * sh_g[col] + sh_be[col];
                    float v1 = (acc[m][n][h * 2 + 1] - mu[m][h]) * rstd[m][h] * sh_g[col + 1] + sh_be[col + 1];
                    v0 = v0 > 0.f ? v0 : LEAKY * v0;
                    v1 = v1 > 0.f ? v1 : LEAKY * v1;
                    p0[m][h] += v0 * sh_w3[col * 2 + 0] + v1 * sh_w3[(col + 1) * 2 + 0];
                    p1[m][h] += v0 * sh_w3[col * 2 + 1] + v1 * sh_w3[(col + 1) * 2 + 1];
                }
            }
#pragma unroll
        for (int o = 1; o <= 2; o <<= 1) {
#pragma unroll
            for (int m = 0; m < 2; m++)
#pragma unroll
                for (int h = 0; h < 2; h++) {
                    p0[m][h] += __shfl_xor_sync(0xffffffffu, p0[m][h], o);
                    p1[m][h] += __shfl_xor_sync(0xffffffffu, p1[m][h], o);
                }
        }
        if (lt == 0) {
#pragma unroll
            for (int m = 0; m < 2; m++)
#pragma unroll
                for (int h = 0; h < 2; h++) {
                    sh_s0[mbase + m * 16 + lg + h * 8][warp_n] = p0[m][h];
                    sh_s1[mbase + m * 16 + lg + h * 8][warp_n] = p1[m][h];
                }
        }
        __syncthreads();
        if (tid < 128) {
            int gr = rowBase + tid;
            if (gr < N_NODES) {
                float no = g_norm_out[gr];
                float2 p = { no * (sh_s0[tid][0] + sh_s0[tid][1]),
                             no * (sh_s1[tid][0] + sh_s1[tid][1]) };
                g_proj[gr] = p;
            }
        }
    }
}

// ---------------- final aggregation over 2-dim projected features ----------------
__global__ void agg2_kernel(const float* __restrict__ b3, float* __restrict__ out) {
    int node = blockIdx.x * blockDim.x + threadIdx.x;
    if (node >= N_NODES) return;
    int beg = g_row_start[node];
    int end = g_row_start[node + 1];
    float a0 = 0.f, a1 = 0.f;
    for (int e = beg; e < end; e++) {
        float2 p = g_proj[g_col[e]];
        a0 += p.x;
        a1 += p.y;
    }
    float ni = g_norm_in[node];
    out[node * 2 + 0] = ni * a0 + b3[0];
    out[node * 2 + 1] = ni * a1 + b3[1];
}

// ---------------- launch: pure kernel launches, no runtime API ----------------
extern "C" void kernel_launch(void* const* d_in, const int* in_sizes, int n_in,
                              void* d_out, int out_size) {
    const float* feat = (const float*)d_in[0];
    const int*   src  = (const int*)d_in[1];   // int32 (JAX x64 disabled)
    const int*   dst  = (const int*)d_in[2];
    const float* W1  = (const float*)d_in[3];
    const float* b1  = (const float*)d_in[4];
    const float* W2  = (const float*)d_in[5];
    const float* b2  = (const float*)d_in[6];
    const float* W3  = (const float*)d_in[7];
    const float* b3  = (const float*)d_in[8];
    const float* g1  = (const float*)d_in[9];
    const float* be1 = (const float*)d_in[10];
    const float* g2  = (const float*)d_in[11];
    const float* be2 = (const float*)d_in[12];
    float* out = (float*)d_out;

    const int NB_N  = (N_NODES + 255) / 256;
    const int NB_E4 = (N_EDGES / 4 + 255) / 256;
    const int NB_W  = (N_NODES + 7) / 8;
    const int NB_G  = (N_NODES + 127) / 128;   // 391

    // graph structure
    zero_deg_kernel<<<NB_N, 256>>>();
    count_deg_kernel<<<NB_E4, 256>>>((const int4*)src, (const int4*)dst);
    scan_bsum_kernel<<<N_SBLK, SCAN_BLK>>>();
    scan_partials_kernel<<<1, 256>>>();
    scan_final_kernel<<<N_SBLK, SCAN_BLK>>>();
    fill_csr_kernel<<<NB_E4, 256>>>((const int4*)src, (const int4*)dst);

    // layer 1: agg -> tf32 mma gemm + bias + LN + leaky -> g_x
    agg128_kernel<false><<<NB_W, 256>>>(feat);
    gemm_mma_kernel<0><<<NB_G, 256>>>(W1, b1, g1, be1, nullptr);

    // layer 2: agg -> tf32 mma gemm + bias + LN + leaky + W3 projection -> g_proj
    agg128_kernel<true><<<NB_W, 256>>>(feat);
    gemm_mma_kernel<1><<<NB_G, 256>>>(W2, b2, g2, be2, W3);

    // layer 3 aggregation
    agg2_kernel<<<NB_N, 256>>>(b3, out);
}

// round 12
// speedup vs baseline: 1.2778x; 1.0098x over previous
#include <cuda_runtime.h>
#include <cuda_bf16.h>
#include <stdint.h>

#define N_NODES 50000
#define N_EDGES 800000
#define DIM 128
#define VDIM 32            // DIM/4 float4 per row
#define LEAKY 0.01f
#define LN_EPS 1e-5f

#define SCAN_BLK 256
#define N_SBLK ((N_NODES + SCAN_BLK - 1) / SCAN_BLK)   // 196

// ---------------- scratch (device globals; allocation is forbidden) ----------------
__device__ int    g_deg_in[N_NODES];
__device__ int    g_deg_out[N_NODES];
__device__ float  g_norm_in[N_NODES];
__device__ float  g_norm_out[N_NODES];
__device__ int    g_row_start[N_NODES + 1];
__device__ int    g_fill[N_NODES];
__device__ int    g_col[N_EDGES];
__device__ int    g_bsum[N_SBLK];

__device__ float4 g_agg[(size_t)N_NODES * VDIM];   // aggregation output (fp32)
__device__ float4 g_x[(size_t)N_NODES * VDIM];     // post LN+leaky features (fp32)
__device__ float2 g_proj[N_NODES];                 // layer-3 projected features
__device__ uint2  g_w2a[128 * 128];                // W1 pre-split (hi,lo) tf32
__device__ uint2  g_w2b[128 * 128];                // W2 pre-split

__device__ __forceinline__ int clamp_idx(int v) {
    v = v < 0 ? 0 : v;
    return v >= N_NODES ? N_NODES - 1 : v;
}

// ---------------- tf32 mma helpers (base PTX, plain sm_100-safe) ----------------
__device__ __forceinline__ uint32_t cvt_tf32(float f) {
    uint32_t r;
    asm("cvt.rna.tf32.f32 %0, %1;" : "=r"(r) : "f"(f));
    return r;
}
__device__ __forceinline__ void mma8(float* c, const uint32_t* a, uint32_t b0, uint32_t b1) {
    asm volatile(
        "mma.sync.aligned.m16n8k8.row.col.f32.tf32.tf32.f32 "
        "{%0,%1,%2,%3}, {%4,%5,%6,%7}, {%8,%9}, {%0,%1,%2,%3};"
        : "+f"(c[0]), "+f"(c[1]), "+f"(c[2]), "+f"(c[3])
        : "r"(a[0]), "r"(a[1]), "r"(a[2]), "r"(a[3]), "r"(b0), "r"(b1));
}

// ---------------- setup ----------------
__global__ void zero_deg_kernel() {
    int i = blockIdx.x * blockDim.x + threadIdx.x;
    if (i < N_NODES) { g_deg_in[i] = 0; g_deg_out[i] = 0; }
}

__global__ void count_deg_kernel(const int4* __restrict__ src4,
                                 const int4* __restrict__ dst4) {
    int t = blockIdx.x * blockDim.x + threadIdx.x;
    if (t >= N_EDGES / 4) return;
    int4 s = src4[t];
    int4 d = dst4[t];
    atomicAdd(&g_deg_out[clamp_idx(s.x)], 1);
    atomicAdd(&g_deg_out[clamp_idx(s.y)], 1);
    atomicAdd(&g_deg_out[clamp_idx(s.z)], 1);
    atomicAdd(&g_deg_out[clamp_idx(s.w)], 1);
    atomicAdd(&g_deg_in[clamp_idx(d.x)], 1);
    atomicAdd(&g_deg_in[clamp_idx(d.y)], 1);
    atomicAdd(&g_deg_in[clamp_idx(d.z)], 1);
    atomicAdd(&g_deg_in[clamp_idx(d.w)], 1);
}

// pre-split a 128x128 weight matrix into packed (hi,lo) tf32.
// WSEL selects the destination table in DEVICE code (no host symbol refs).
template <int WSEL>
__global__ void split_w_kernel(const float* __restrict__ W) {
    uint2* out = (WSEL == 0) ? g_w2a : g_w2b;
    int t = blockIdx.x * blockDim.x + threadIdx.x;
    if (t >= 128 * 128) return;
    float w = W[t];
    uint32_t hi = cvt_tf32(w);
    uint32_t lo = cvt_tf32(w - __uint_as_float(hi));
    uint2 p = { hi, lo };
    out[t] = p;
}

__global__ __launch_bounds__(SCAN_BLK)
void scan_bsum_kernel() {
    int i = blockIdx.x * SCAN_BLK + threadIdx.x;
    int v = (i < N_NODES) ? g_deg_in[i] : 0;
#pragma unroll
    for (int o = 16; o; o >>= 1) v += __shfl_xor_sync(0xffffffffu, v, o);
    __shared__ int wsum[SCAN_BLK / 32];
    if ((threadIdx.x & 31) == 0) wsum[threadIdx.x >> 5] = v;
    __syncthreads();
    if (threadIdx.x == 0) {
        int s = 0;
#pragma unroll
        for (int w = 0; w < SCAN_BLK / 32; w++) s += wsum[w];
        g_bsum[blockIdx.x] = s;
    }
}

// one-block exclusive scan of the 196 partials (warp-shuffle version)
__global__ __launch_bounds__(256)
void scan_partials_kernel() {
    __shared__ int wsum[8];
    __shared__ int woff[8];
    int tid = threadIdx.x;
    int lane = tid & 31, wid = tid >> 5;
    int v = (tid < N_SBLK) ? g_bsum[tid] : 0;
    int incl = v;
#pragma unroll
    for (int o = 1; o < 32; o <<= 1) {
        int t = __shfl_up_sync(0xffffffffu, incl, o);
        if (lane >= o) incl += t;
    }
    if (lane == 31) wsum[wid] = incl;
    __syncthreads();
    if (wid == 0 && lane < 8) {
        int w = wsum[lane];
        int wi = w;
#pragma unroll
        for (int o = 1; o < 8; o <<= 1) {
            int t = __shfl_up_sync(0xffu, wi, o);
            if (lane >= o) wi += t;
        }
        woff[lane] = wi - w;
        if (lane == 7) g_row_start[N_NODES] = wi;   // total edge count
    }
    __syncthreads();
    if (tid < N_SBLK) g_bsum[tid] = woff[wid] + incl - v;   // exclusive prefix
}

__global__ __launch_bounds__(SCAN_BLK)
void scan_final_kernel() {
    int tid = threadIdx.x;
    int i = blockIdx.x * SCAN_BLK + tid;
    int lane = tid & 31, wid = tid >> 5;
    int v = (i < N_NODES) ? g_deg_in[i] : 0;
    int incl = v;
#pragma unroll
    for (int o = 1; o < 32; o <<= 1) {
        int t = __shfl_up_sync(0xffffffffu, incl, o);
        if (lane >= o) incl += t;
    }
    __shared__ int wsum[SCAN_BLK / 32];
    __shared__ int woff[SCAN_BLK / 32];
    if (lane == 31) wsum[wid] = incl;
    __syncthreads();
    if (tid == 0) {
        int s = 0;
#pragma unroll
        for (int w = 0; w < SCAN_BLK / 32; w++) { woff[w] = s; s += wsum[w]; }
    }
    __syncthreads();
    if (i < N_NODES) {
        int excl = incl - v + woff[wid] + g_bsum[blockIdx.x];
        g_row_start[i] = excl;
        g_fill[i] = excl;
        g_norm_out[i] = rsqrtf(fmaxf((float)g_deg_out[i], 1.0f));
        g_norm_in[i]  = rsqrtf(fmaxf((float)v, 1.0f));
    }
}

__global__ void fill_csr_kernel(const int4* __restrict__ src4,
                                const int4* __restrict__ dst4) {
    int t = blockIdx.x * blockDim.x + threadIdx.x;
    if (t >= N_EDGES / 4) return;
    int4 s = src4[t];
    int4 d = dst4[t];
    int p;
    p = atomicAdd(&g_fill[clamp_idx(d.x)], 1); g_col[p] = clamp_idx(s.x);
    p = atomicAdd(&g_fill[clamp_idx(d.y)], 1); g_col[p] = clamp_idx(s.y);
    p = atomicAdd(&g_fill[clamp_idx(d.z)], 1); g_col[p] = clamp_idx(s.z);
    p = atomicAdd(&g_fill[clamp_idx(d.w)], 1); g_col[p] = clamp_idx(s.w);
}

// ---------------- aggregation: warp per node, 128 feats as float4/lane ----------------
template <bool USE_GX>
__global__ __launch_bounds__(256)
void agg128_kernel(const float* __restrict__ feat) {
    int node = blockIdx.x * (blockDim.x >> 5) + (threadIdx.x >> 5);
    if (node >= N_NODES) return;
    int lane = threadIdx.x & 31;
    int beg = g_row_start[node];
    int end = g_row_start[node + 1];
    float ax = 0.f, ay = 0.f, az = 0.f, aw = 0.f;
#pragma unroll 4
    for (int e = beg; e < end; e++) {
        int c = g_col[e];
        float w = g_norm_out[c];
        float4 v;
        if (USE_GX) v = g_x[(size_t)c * VDIM + lane];
        else        v = ((const float4*)(feat + (size_t)c * DIM))[lane];
        ax = fmaf(w, v.x, ax);
        ay = fmaf(w, v.y, ay);
        az = fmaf(w, v.z, az);
        aw = fmaf(w, v.w, aw);
    }
    float ni = g_norm_in[node];
    float4 o = { ax * ni, ay * ni, az * ni, aw * ni };
    g_agg[(size_t)node * VDIM + lane] = o;
}

// pack two fp32 into (hi,lo)(hi,lo) tf32 uint4 — pure scalar, no local arrays
__device__ __forceinline__ uint4 pack2_tf32(float x, float y) {
    uint32_t hx = cvt_tf32(x);
    uint32_t hy = cvt_tf32(y);
    uint4 p;
    p.x = hx; p.y = cvt_tf32(x - __uint_as_float(hx));
    p.z = hy; p.w = cvt_tf32(y - __uint_as_float(hy));
    return p;
}

// ---------------- tf32 mma GEMM + bias + LN + leaky (+ W3 projection) -----------------
// Block tile 128x128, K=128 in 8 chunks of 16. 8 warps: 4 along M, 2 along N.
// 3-term tf32 split (hi*hi + hi*lo + lo*hi) with (hi,lo) PACKED in SMEM -> LDS64.
// MODE 0 -> g_x. MODE 1 -> g_proj (W3 projection with norm_out).
// WSEL picks the pre-split weight table in DEVICE code.
#define AP2 20     // A pitch in uint2
#define BP2 132    // B pitch in uint2
template <int MODE, int WSEL>
__global__ __launch_bounds__(256)
void gemm_mma_kernel(const float* __restrict__ b,
                     const float* __restrict__ g, const float* __restrict__ be,
                     const float* __restrict__ W3) {
    __shared__ uint2 As[128][AP2];                 // 20 KB   (k index 0..15)
    __shared__ uint2 Bs[16][BP2];                  // 16.9 KB (col 0..127)
    __shared__ float sh_b[128], sh_g[128], sh_be[128], sh_w3[256];
    __shared__ float sh_s0[128][2], sh_s1[128][2];

    const uint2* __restrict__ W2 = (WSEL == 0) ? g_w2a : g_w2b;

    int tid = threadIdx.x;
    int wid = tid >> 5, lane = tid & 31;
    int lg = lane >> 2, lt = lane & 3;
    int warp_m = wid & 3, warp_n = wid >> 2;
    int mbase = warp_m * 32, nbase = warp_n * 64;
    int rowBase = blockIdx.x * 128;

    if (tid < 128) { sh_b[tid] = b[tid]; sh_g[tid] = g[tid]; sh_be[tid] = be[tid]; }
    if (MODE == 1 && tid >= 128) {
        sh_w3[2 * (tid - 128)] = W3[2 * (tid - 128)];
        sh_w3[2 * (tid - 128) + 1] = W3[2 * (tid - 128) + 1];
    }

    float acc[2][8][4];
#pragma unroll
    for (int m = 0; m < 2; m++)
#pragma unroll
        for (int n = 0; n < 8; n++)
#pragma unroll
            for (int e = 0; e < 4; e++) acc[m][n][e] = 0.f;

    const float* Af = (const float*)g_agg;
    int a_row = tid >> 1;                 // staging: 2 threads per A row
    int a_half = tid & 1;                 // k-half (8 elems)
    int b_k = tid >> 4;                   // staging: 16 threads per B row
    int b_j = tid & 15;                   // uint4 group

    for (int kc = 0; kc < 8; kc++) {
        // ---- stage A chunk 128x16: LDG128 x2, scalar split, 4x STS128 ----
        {
            int gr = rowBase + a_row;
            float4 v0 = make_float4(0.f, 0.f, 0.f, 0.f), v1 = v0;
            if (gr < N_NODES) {
                const float* p = Af + (size_t)gr * DIM + kc * 16 + a_half * 8;
                v0 = *(const float4*)p;
                v1 = *(const float4*)(p + 4);
            }
            uint4* dst = (uint4*)&As[a_row][a_half * 8];
            dst[0] = pack2_tf32(v0.x, v0.y);
            dst[1] = pack2_tf32(v0.z, v0.w);
            dst[2] = pack2_tf32(v1.x, v1.y);
            dst[3] = pack2_tf32(v1.z, v1.w);
        }
        // ---- stage B chunk 16x128: pure uint4 copy from pre-split table ----
        {
            const uint4* srcw = (const uint4*)(W2 + (size_t)(kc * 16 + b_k) * 128);
            uint4* dstw = (uint4*)&Bs[b_k][0];
#pragma unroll
            for (int r = 0; r < 4; r++) dstw[b_j + r * 16] = srcw[b_j + r * 16];
        }
        __syncthreads();

#pragma unroll
        for (int ks = 0; ks < 2; ks++) {
            int kb = ks * 8;
            uint32_t a_hi[2][4], a_lo[2][4];
#pragma unroll
            for (int m = 0; m < 2; m++) {
                int r0 = mbase + m * 16 + lg;
                uint2 p0 = As[r0][kb + lt];
                uint2 p1 = As[r0 + 8][kb + lt];
                uint2 p2 = As[r0][kb + lt + 4];
                uint2 p3 = As[r0 + 8][kb + lt + 4];
                a_hi[m][0] = p0.x; a_lo[m][0] = p0.y;
                a_hi[m][1] = p1.x; a_lo[m][1] = p1.y;
                a_hi[m][2] = p2.x; a_lo[m][2] = p2.y;
                a_hi[m][3] = p3.x; a_lo[m][3] = p3.y;
            }
            // B fragments loaded per-n (keeps live registers low)
#pragma unroll
            for (int n = 0; n < 8; n++) {
                int c0 = nbase + n * 8 + lg;
                uint2 q0 = Bs[kb + lt][c0];
                uint2 q1 = Bs[kb + lt + 4][c0];
#pragma unroll
                for (int m = 0; m < 2; m++) {
                    mma8(acc[m][n], a_hi[m], q0.x, q1.x);   // hi*hi
                    mma8(acc[m][n], a_hi[m], q0.y, q1.y);   // hi*lo
                    mma8(acc[m][n], a_lo[m], q0.x, q1.x);   // lo*hi
                }
            }
        }
        __syncthreads();
    }

    // ---- epilogue: bias, LN stats via shfl + cross-warp SMEM, leaky, output ----
#pragma unroll
    for (int m = 0; m < 2; m++)
#pragma unroll
        for (int n = 0; n < 8; n++) {
            int col = nbase + n * 8 + 2 * lt;
            acc[m][n][0] += sh_b[col];
            acc[m][n][1] += sh_b[col + 1];
            acc[m][n][2] += sh_b[col];
            acc[m][n][3] += sh_b[col + 1];
        }

    float rs[2][2];
#pragma unroll
    for (int m = 0; m < 2; m++) {
        float s0 = 0.f, s1 = 0.f;
#pragma unroll
        for (int n = 0; n < 8; n++) {
            s0 += acc[m][n][0] + acc[m][n][1];
            s1 += acc[m][n][2] + acc[m][n][3];
        }
        rs[m][0] = s0; rs[m][1] = s1;
    }
#pragma unroll
    for (int o = 1; o <= 2; o <<= 1) {
#pragma unroll
        for (int m = 0; m < 2; m++) {
            rs[m][0] += __shfl_xor_sync(0xffffffffu, rs[m][0], o);
            rs[m][1] += __shfl_xor_sync(0xffffffffu, rs[m][1], o);
        }
    }
    if (lt == 0) {
#pragma unroll
        for (int m = 0; m < 2; m++) {
            sh_s0[mbase + m * 16 + lg][warp_n] = rs[m][0];
            sh_s0[mbase + m * 16 + lg + 8][warp_n] = rs[m][1];
        }
    }
    __syncthreads();

    float mu[2][2];
#pragma unroll
    for (int m = 0; m < 2; m++) {
        int r0 = mbase + m * 16 + lg;
        mu[m][0] = (sh_s0[r0][0] + sh_s0[r0][1]) * (1.f / DIM);
        mu[m][1] = (sh_s0[r0 + 8][0] + sh_s0[r0 + 8][1]) * (1.f / DIM);
    }

    float qs[2][2];
#pragma unroll
    for (int m = 0; m < 2; m++) {
        float q0 = 0.f, q1 = 0.f;
#pragma unroll
        for (int n = 0; n < 8; n++) {
            float d;
            d = acc[m][n][0] - mu[m][0]; q0 += d * d;
            d = acc[m][n][1] - mu[m][0]; q0 += d * d;
            d = acc[m][n][2] - mu[m][1]; q1 += d * d;
            d = acc[m][n][3] - mu[m][1]; q1 += d * d;
        }
        qs[m][0] = q0; qs[m][1] = q1;
    }
#pragma unroll
    for (int o = 1; o <= 2; o <<= 1) {
#pragma unroll
        for (int m = 0; m < 2; m++) {
            qs[m][0] += __shfl_xor_sync(0xffffffffu, qs[m][0], o);
            qs[m][1] += __shfl_xor_sync(0xffffffffu, qs[m][1], o);
        }
    }
    if (lt == 0) {
#pragma unroll
        for (int m = 0; m < 2; m++) {
            sh_s1[mbase + m * 16 + lg][warp_n] = qs[m][0];
            sh_s1[mbase + m * 16 + lg + 8][warp_n] = qs[m][1];
        }
    }
    __syncthreads();

    float rstd[2][2];
#pragma unroll
    for (int m = 0; m < 2; m++) {
        int r0 = mbase + m * 16 + lg;
        rstd[m][0] = rsqrtf((sh_s1[r0][0] + sh_s1[r0][1]) * (1.f / DIM) + LN_EPS);
        rstd[m][1] = rsqrtf((sh_s1[r0 + 8][0] + sh_s1[r0 + 8][1]) * (1.f / DIM) + LN_EPS);
    }

    if (MODE == 0) {
        float* xf = (float*)g_x;
#pragma unroll
        for (int m = 0; m < 2; m++) {
            int r0 = mbase + m * 16 + lg;
#pragma unroll
            for (int h = 0; h < 2; h++) {
                int gr = rowBase + r0 + h * 8;
                if (gr < N_NODES) {
#pragma unroll
                    for (int n = 0; n < 8; n++) {
                        int col = nbase + n * 8 + 2 * lt;
                        float v0 = (acc[m][n][h * 2 + 0] - mu[m][h]) * rstd[m][h] * sh_g[col] + sh_be[col];
                        float v1 = (acc[m][n][h * 2 + 1] - mu[m][h]) * rstd[m][h] * sh_g[col + 1] + sh_be[col + 1];
                        v0 = v0 > 0.f ? v0 : LEAKY * v0;
                        v1 = v1 > 0.f ? v1 : LEAKY * v1;
                        float2 p = { v0, v1 };
                        *(float2*)(xf + (size_t)gr * DIM + col) = p;
                    }
                }
            }
        }
    } else {
        __syncthreads();   // reuse sh_s0/sh_s1
        float p0[2][2], p1[2][2];
#pragma unroll
        for (int m = 0; m < 2; m++)
#pragma unroll
            for (int h = 0; h < 2; h++) { p0[m][h] = 0.f; p1[m][h] = 0.f; }
#pragma unroll
        for (int m = 0; m < 2; m++)
#pragma unroll
            for (int n = 0; n < 8; n++) {
                int col = nbase + n * 8 + 2 * lt;
#pragma unroll
                for (int h = 0; h < 2; h++) {
                    float v0 = (acc[m][n][h * 2 + 0] - mu[m][h]) * rstd[m][h] * sh_g[col] + sh_be[col];
                    float v1 = (acc[m][n][h * 2 + 1] - mu[m][h]) * rstd[m][h] * sh_g[col + 1] + sh_be[col + 1];
                    v0 = v0 > 0.f ? v0 : LEAKY * v0;
                    v1 = v1 > 0.f ? v1 : LEAKY * v1;
                    p0[m][h] += v0 * sh_w3[col * 2 + 0] + v1 * sh_w3[(col + 1) * 2 + 0];
                    p1[m][h] += v0 * sh_w3[col * 2 + 1] + v1 * sh_w3[(col + 1) * 2 + 1];
                }
            }
#pragma unroll
        for (int o = 1; o <= 2; o <<= 1) {
#pragma unroll
            for (int m = 0; m < 2; m++)
#pragma unroll
                for (int h = 0; h < 2; h++) {
                    p0[m][h] += __shfl_xor_sync(0xffffffffu, p0[m][h], o);
                    p1[m][h] += __shfl_xor_sync(0xffffffffu, p1[m][h], o);
                }
        }
        if (lt == 0) {
#pragma unroll
            for (int m = 0; m < 2; m++)
#pragma unroll
                for (int h = 0; h < 2; h++) {
                    sh_s0[mbase + m * 16 + lg + h * 8][warp_n] = p0[m][h];
                    sh_s1[mbase + m * 16 + lg + h * 8][warp_n] = p1[m][h];
                }
        }
        __syncthreads();
        if (tid < 128) {
            int gr = rowBase + tid;
            if (gr < N_NODES) {
                float no = g_norm_out[gr];
                float2 p = { no * (sh_s0[tid][0] + sh_s0[tid][1]),
                             no * (sh_s1[tid][0] + sh_s1[tid][1]) };
                g_proj[gr] = p;
            }
        }
    }
}

// ---------------- final aggregation over 2-dim projected features ----------------
__global__ void agg2_kernel(const float* __restrict__ b3, float* __restrict__ out) {
    int node = blockIdx.x * blockDim.x + threadIdx.x;
    if (node >= N_NODES) return;
    int beg = g_row_start[node];
    int end = g_row_start[node + 1];
    float a0 = 0.f, a1 = 0.f;
    for (int e = beg; e < end; e++) {
        float2 p = g_proj[g_col[e]];
        a0 += p.x;
        a1 += p.y;
    }
    float ni = g_norm_in[node];
    out[node * 2 + 0] = ni * a0 + b3[0];
    out[node * 2 + 1] = ni * a1 + b3[1];
}

// ---------------- launch: pure kernel launches, no host refs to device symbols ------
extern "C" void kernel_launch(void* const* d_in, const int* in_sizes, int n_in,
                              void* d_out, int out_size) {
    const float* feat = (const float*)d_in[0];
    const int*   src  = (const int*)d_in[1];   // int32 (JAX x64 disabled)
    const int*   dst  = (const int*)d_in[2];
    const float* W1  = (const float*)d_in[3];
    const float* b1  = (const float*)d_in[4];
    const float* W2  = (const float*)d_in[5];
    const float* b2  = (const float*)d_in[6];
    const float* W3  = (const float*)d_in[7];
    const float* b3  = (const float*)d_in[8];
    const float* g1  = (const float*)d_in[9];
    const float* be1 = (const float*)d_in[10];
    const float* g2  = (const float*)d_in[11];
    const float* be2 = (const float*)d_in[12];
    float* out = (float*)d_out;

    const int NB_N  = (N_NODES + 255) / 256;
    const int NB_E4 = (N_EDGES / 4 + 255) / 256;
    const int NB_W  = (N_NODES + 7) / 8;
    const int NB_G  = (N_NODES + 127) / 128;   // 391

    // graph structure + weight pre-split
    zero_deg_kernel<<<NB_N, 256>>>();
    split_w_kernel<0><<<64, 256>>>(W1);
    split_w_kernel<1><<<64, 256>>>(W2);
    count_deg_kernel<<<NB_E4, 256>>>((const int4*)src, (const int4*)dst);
    scan_bsum_kernel<<<N_SBLK, SCAN_BLK>>>();
    scan_partials_kernel<<<1, 256>>>();
    scan_final_kernel<<<N_SBLK, SCAN_BLK>>>();
    fill_csr_kernel<<<NB_E4, 256>>>((const int4*)src, (const int4*)dst);

    // layer 1: agg -> tf32 mma gemm + bias + LN + leaky -> g_x
    agg128_kernel<false><<<NB_W, 256>>>(feat);
    gemm_mma_kernel<0, 0><<<NB_G, 256>>>(b1, g1, be1, nullptr);

    // layer 2: agg -> tf32 mma gemm + bias + LN + leaky + W3 projection -> g_proj
    agg128_kernel<true><<<NB_W, 256>>>(feat);
    gemm_mma_kernel<1, 1><<<NB_G, 256>>>(b2, g2, be2, W3);

    // layer 3 aggregation
    agg2_kernel<<<NB_N, 256>>>(b3, out);
}

// round 13
// speedup vs baseline: 1.3155x; 1.0295x over previous
#include <cuda_runtime.h>
#include <cuda_bf16.h>
#include <stdint.h>

#define N_NODES 50000
#define N_EDGES 800000
#define DIM 128
#define VDIM 32            // DIM/4 float4 per row
#define LEAKY 0.01f
#define LN_EPS 1e-5f

#define SCAN_BLK 256
#define N_SBLK ((N_NODES + SCAN_BLK - 1) / SCAN_BLK)   // 196

// ---------------- scratch (device globals; allocation is forbidden) ----------------
__device__ int    g_deg_in[N_NODES];
__device__ int    g_deg_out[N_NODES];
__device__ float  g_norm_in[N_NODES];
__device__ float  g_norm_out[N_NODES];
__device__ int    g_row_start[N_NODES + 1];
__device__ int    g_col[N_EDGES];
__device__ int4   g_rank4[N_EDGES / 4];            // per-edge rank within dst bucket
__device__ int    g_bsum[N_SBLK];

__device__ float4 g_agg[(size_t)N_NODES * VDIM];   // aggregation output (fp32)
__device__ float4 g_x[(size_t)N_NODES * VDIM];     // post LN+leaky features (fp32)
__device__ float2 g_proj[N_NODES];                 // layer-3 projected features
__device__ uint2  g_w2a[128 * 128];                // W1 pre-split (hi,lo) tf32
__device__ uint2  g_w2b[128 * 128];                // W2 pre-split

__device__ __forceinline__ int clamp_idx(int v) {
    v = v < 0 ? 0 : v;
    return v >= N_NODES ? N_NODES - 1 : v;
}

// ---------------- tf32 mma helpers (base PTX, plain sm_100-safe) ----------------
__device__ __forceinline__ uint32_t cvt_tf32(float f) {
    uint32_t r;
    asm("cvt.rna.tf32.f32 %0, %1;" : "=r"(r) : "f"(f));
    return r;
}
__device__ __forceinline__ void mma8(float* c, const uint32_t* a, uint32_t b0, uint32_t b1) {
    asm volatile(
        "mma.sync.aligned.m16n8k8.row.col.f32.tf32.tf32.f32 "
        "{%0,%1,%2,%3}, {%4,%5,%6,%7}, {%8,%9}, {%0,%1,%2,%3};"
        : "+f"(c[0]), "+f"(c[1]), "+f"(c[2]), "+f"(c[3])
        : "r"(a[0]), "r"(a[1]), "r"(a[2]), "r"(a[3]), "r"(b0), "r"(b1));
}

// ---------------- setup ----------------
__global__ void zero_deg_kernel() {
    int i = blockIdx.x * blockDim.x + threadIdx.x;
    if (i < N_NODES) { g_deg_in[i] = 0; g_deg_out[i] = 0; }
}

// 8 edges per thread; rank (position within dst bucket) = atomicAdd return, stored coalesced
__global__ void count_deg_kernel(const int4* __restrict__ src4,
                                 const int4* __restrict__ dst4) {
    int t = blockIdx.x * blockDim.x + threadIdx.x;
    if (t >= N_EDGES / 8) return;
    int4 s0 = src4[t * 2], s1 = src4[t * 2 + 1];
    int4 d0 = dst4[t * 2], d1 = dst4[t * 2 + 1];
    atomicAdd(&g_deg_out[clamp_idx(s0.x)], 1);
    atomicAdd(&g_deg_out[clamp_idx(s0.y)], 1);
    atomicAdd(&g_deg_out[clamp_idx(s0.z)], 1);
    atomicAdd(&g_deg_out[clamp_idx(s0.w)], 1);
    atomicAdd(&g_deg_out[clamp_idx(s1.x)], 1);
    atomicAdd(&g_deg_out[clamp_idx(s1.y)], 1);
    atomicAdd(&g_deg_out[clamp_idx(s1.z)], 1);
    atomicAdd(&g_deg_out[clamp_idx(s1.w)], 1);
    int4 r0, r1;
    r0.x = atomicAdd(&g_deg_in[clamp_idx(d0.x)], 1);
    r0.y = atomicAdd(&g_deg_in[clamp_idx(d0.y)], 1);
    r0.z = atomicAdd(&g_deg_in[clamp_idx(d0.z)], 1);
    r0.w = atomicAdd(&g_deg_in[clamp_idx(d0.w)], 1);
    r1.x = atomicAdd(&g_deg_in[clamp_idx(d1.x)], 1);
    r1.y = atomicAdd(&g_deg_in[clamp_idx(d1.y)], 1);
    r1.z = atomicAdd(&g_deg_in[clamp_idx(d1.z)], 1);
    r1.w = atomicAdd(&g_deg_in[clamp_idx(d1.w)], 1);
    g_rank4[t * 2]     = r0;
    g_rank4[t * 2 + 1] = r1;
}

__global__ __launch_bounds__(SCAN_BLK)
void scan_bsum_kernel() {
    int i = blockIdx.x * SCAN_BLK + threadIdx.x;
    int v = (i < N_NODES) ? g_deg_in[i] : 0;
#pragma unroll
    for (int o = 16; o; o >>= 1) v += __shfl_xor_sync(0xffffffffu, v, o);
    __shared__ int wsum[SCAN_BLK / 32];
    if ((threadIdx.x & 31) == 0) wsum[threadIdx.x >> 5] = v;
    __syncthreads();
    if (threadIdx.x == 0) {
        int s = 0;
#pragma unroll
        for (int w = 0; w < SCAN_BLK / 32; w++) s += wsum[w];
        g_bsum[blockIdx.x] = s;
    }
}

// block 0: exclusive scan of the 196 partials.  blocks 1..128: W1/W2 tf32 pre-split.
__global__ __launch_bounds__(256)
void scan_partials_split_kernel(const float* __restrict__ W1,
                                const float* __restrict__ W2) {
    if (blockIdx.x == 0) {
        __shared__ int wsum[8];
        __shared__ int woff[8];
        int tid = threadIdx.x;
        int lane = tid & 31, wid = tid >> 5;
        int v = (tid < N_SBLK) ? g_bsum[tid] : 0;
        int incl = v;
#pragma unroll
        for (int o = 1; o < 32; o <<= 1) {
            int t = __shfl_up_sync(0xffffffffu, incl, o);
            if (lane >= o) incl += t;
        }
        if (lane == 31) wsum[wid] = incl;
        __syncthreads();
        if (wid == 0 && lane < 8) {
            int w = wsum[lane];
            int wi = w;
#pragma unroll
            for (int o = 1; o < 8; o <<= 1) {
                int t = __shfl_up_sync(0xffu, wi, o);
                if (lane >= o) wi += t;
            }
            woff[lane] = wi - w;
            if (lane == 7) g_row_start[N_NODES] = wi;   // total edge count
        }
        __syncthreads();
        if (tid < N_SBLK) g_bsum[tid] = woff[wid] + incl - v;   // exclusive prefix
    } else {
        int bi = blockIdx.x - 1;                 // 0..127
        const float* W = (bi < 64) ? W1 : W2;
        uint2* out = (bi < 64) ? g_w2a : g_w2b;
        int t = (bi & 63) * 256 + threadIdx.x;   // 0..16383
        float w = W[t];
        uint32_t hi = cvt_tf32(w);
        uint32_t lo = cvt_tf32(w - __uint_as_float(hi));
        uint2 p = { hi, lo };
        out[t] = p;
    }
}

__global__ __launch_bounds__(SCAN_BLK)
void scan_final_kernel() {
    int tid = threadIdx.x;
    int i = blockIdx.x * SCAN_BLK + tid;
    int lane = tid & 31, wid = tid >> 5;
    int v = (i < N_NODES) ? g_deg_in[i] : 0;
    int incl = v;
#pragma unroll
    for (int o = 1; o < 32; o <<= 1) {
        int t = __shfl_up_sync(0xffffffffu, incl, o);
        if (lane >= o) incl += t;
    }
    __shared__ int wsum[SCAN_BLK / 32];
    __shared__ int woff[SCAN_BLK / 32];
    if (lane == 31) wsum[wid] = incl;
    __syncthreads();
    if (tid == 0) {
        int s = 0;
#pragma unroll
        for (int w = 0; w < SCAN_BLK / 32; w++) { woff[w] = s; s += wsum[w]; }
    }
    __syncthreads();
    if (i < N_NODES) {
        int excl = incl - v + woff[wid] + g_bsum[blockIdx.x];
        g_row_start[i] = excl;
        g_norm_out[i] = rsqrtf(fmaxf((float)g_deg_out[i], 1.0f));
        g_norm_in[i]  = rsqrtf(fmaxf((float)v, 1.0f));
    }
}

// atomic-free CSR fill using precomputed ranks
__global__ void fill_csr_kernel(const int4* __restrict__ src4,
                                const int4* __restrict__ dst4) {
    int t = blockIdx.x * blockDim.x + threadIdx.x;
    if (t >= N_EDGES / 4) return;
    int4 s = src4[t];
    int4 d = dst4[t];
    int4 r = g_rank4[t];
    g_col[g_row_start[clamp_idx(d.x)] + r.x] = clamp_idx(s.x);
    g_col[g_row_start[clamp_idx(d.y)] + r.y] = clamp_idx(s.y);
    g_col[g_row_start[clamp_idx(d.z)] + r.z] = clamp_idx(s.z);
    g_col[g_row_start[clamp_idx(d.w)] + r.w] = clamp_idx(s.w);
}

// ---------------- aggregation: warp per node, 128 feats as float4/lane ----------------
template <bool USE_GX>
__global__ __launch_bounds__(256)
void agg128_kernel(const float* __restrict__ feat) {
    int node = blockIdx.x * (blockDim.x >> 5) + (threadIdx.x >> 5);
    if (node >= N_NODES) return;
    int lane = threadIdx.x & 31;
    int beg = g_row_start[node];
    int end = g_row_start[node + 1];
    float ax = 0.f, ay = 0.f, az = 0.f, aw = 0.f;
#pragma unroll 8
    for (int e = beg; e < end; e++) {
        int c = g_col[e];
        float w = g_norm_out[c];
        float4 v;
        if (USE_GX) v = g_x[(size_t)c * VDIM + lane];
        else        v = ((const float4*)(feat + (size_t)c * DIM))[lane];
        ax = fmaf(w, v.x, ax);
        ay = fmaf(w, v.y, ay);
        az = fmaf(w, v.z, az);
        aw = fmaf(w, v.w, aw);
    }
    float ni = g_norm_in[node];
    float4 o = { ax * ni, ay * ni, az * ni, aw * ni };
    g_agg[(size_t)node * VDIM + lane] = o;
}

// pack two fp32 into (hi,lo)(hi,lo) tf32 uint4 — pure scalar, no local arrays
__device__ __forceinline__ uint4 pack2_tf32(float x, float y) {
    uint32_t hx = cvt_tf32(x);
    uint32_t hy = cvt_tf32(y);
    uint4 p;
    p.x = hx; p.y = cvt_tf32(x - __uint_as_float(hx));
    p.z = hy; p.w = cvt_tf32(y - __uint_as_float(hy));
    return p;
}

// ---------------- tf32 mma GEMM + bias + LN + leaky (+ W3 projection) -----------------
// Block tile 128x128, K=128 in 8 chunks of 16. 8 warps: 4 along M, 2 along N.
// 3-term tf32 split (hi*hi + hi*lo + lo*hi) with (hi,lo) PACKED in SMEM -> LDS64.
// MODE 0 -> g_x. MODE 1 -> g_proj (W3 projection with norm_out).
// WSEL picks the pre-split weight table in DEVICE code.
#define AP2 20     // A pitch in uint2
#define BP2 132    // B pitch in uint2
template <int MODE, int WSEL>
__global__ __launch_bounds__(256)
void gemm_mma_kernel(const float* __restrict__ b,
                     const float* __restrict__ g, const float* __restrict__ be,
                     const float* __restrict__ W3) {
    __shared__ uint2 As[128][AP2];                 // 20 KB   (k index 0..15)
    __shared__ uint2 Bs[16][BP2];                  // 16.9 KB (col 0..127)
    __shared__ float sh_b[128], sh_g[128], sh_be[128], sh_w3[256];
    __shared__ float sh_s0[128][2], sh_s1[128][2];

    const uint2* __restrict__ W2 = (WSEL == 0) ? g_w2a : g_w2b;

    int tid = threadIdx.x;
    int wid = tid >> 5, lane = tid & 31;
    int lg = lane >> 2, lt = lane & 3;
    int warp_m = wid & 3, warp_n = wid >> 2;
    int mbase = warp_m * 32, nbase = warp_n * 64;
    int rowBase = blockIdx.x * 128;

    if (tid < 128) { sh_b[tid] = b[tid]; sh_g[tid] = g[tid]; sh_be[tid] = be[tid]; }
    if (MODE == 1 && tid >= 128) {
        sh_w3[2 * (tid - 128)] = W3[2 * (tid - 128)];
        sh_w3[2 * (tid - 128) + 1] = W3[2 * (tid - 128) + 1];
    }

    float acc[2][8][4];
#pragma unroll
    for (int m = 0; m < 2; m++)
#pragma unroll
        for (int n = 0; n < 8; n++)
#pragma unroll
            for (int e = 0; e < 4; e++) acc[m][n][e] = 0.f;

    const float* Af = (const float*)g_agg;
    int a_row = tid >> 1;                 // staging: 2 threads per A row
    int a_half = tid & 1;                 // k-half (8 elems)
    int b_k = tid >> 4;                   // staging: 16 threads per B row
    int b_j = tid & 15;                   // uint4 group

    for (int kc = 0; kc < 8; kc++) {
        // ---- stage A chunk 128x16: LDG128 x2, scalar split, 4x STS128 ----
        {
            int gr = rowBase + a_row;
            float4 v0 = make_float4(0.f, 0.f, 0.f, 0.f), v1 = v0;
            if (gr < N_NODES) {
                const float* p = Af + (size_t)gr * DIM + kc * 16 + a_half * 8;
                v0 = *(const float4*)p;
                v1 = *(const float4*)(p + 4);
            }
            uint4* dst = (uint4*)&As[a_row][a_half * 8];
            dst[0] = pack2_tf32(v0.x, v0.y);
            dst[1] = pack2_tf32(v0.z, v0.w);
            dst[2] = pack2_tf32(v1.x, v1.y);
            dst[3] = pack2_tf32(v1.z, v1.w);
        }
        // ---- stage B chunk 16x128: pure uint4 copy from pre-split table ----
        {
            const uint4* srcw = (const uint4*)(W2 + (size_t)(kc * 16 + b_k) * 128);
            uint4* dstw = (uint4*)&Bs[b_k][0];
#pragma unroll
            for (int r = 0; r < 4; r++) dstw[b_j + r * 16] = srcw[b_j + r * 16];
        }
        __syncthreads();

#pragma unroll
        for (int ks = 0; ks < 2; ks++) {
            int kb = ks * 8;
            uint32_t a_hi[2][4], a_lo[2][4];
#pragma unroll
            for (int m = 0; m < 2; m++) {
                int r0 = mbase + m * 16 + lg;
                uint2 p0 = As[r0][kb + lt];
                uint2 p1 = As[r0 + 8][kb + lt];
                uint2 p2 = As[r0][kb + lt + 4];
                uint2 p3 = As[r0 + 8][kb + lt + 4];
                a_hi[m][0] = p0.x; a_lo[m][0] = p0.y;
                a_hi[m][1] = p1.x; a_lo[m][1] = p1.y;
                a_hi[m][2] = p2.x; a_lo[m][2] = p2.y;
                a_hi[m][3] = p3.x; a_lo[m][3] = p3.y;
            }
            // B fragments loaded per-n (keeps live registers low)
#pragma unroll
            for (int n = 0; n < 8; n++) {
                int c0 = nbase + n * 8 + lg;
                uint2 q0 = Bs[kb + lt][c0];
                uint2 q1 = Bs[kb + lt + 4][c0];
#pragma unroll
                for (int m = 0; m < 2; m++) {
                    mma8(acc[m][n], a_hi[m], q0.x, q1.x);   // hi*hi
                    mma8(acc[m][n], a_hi[m], q0.y, q1.y);   // hi*lo
                    mma8(acc[m][n], a_lo[m], q0.x, q1.x);   // lo*hi
                }
            }
        }
        __syncthreads();
    }

    // ---- epilogue: bias, LN stats via shfl + cross-warp SMEM, leaky, output ----
#pragma unroll
    for (int m = 0; m < 2; m++)
#pragma unroll
        for (int n = 0; n < 8; n++) {
            int col = nbase + n * 8 + 2 * lt;
            acc[m][n][0] += sh_b[col];
            acc[m][n][1] += sh_b[col + 1];
            acc[m][n][2] += sh_b[col];
            acc[m][n][3] += sh_b[col + 1];
        }

    float rs[2][2];
#pragma unroll
    for (int m = 0; m < 2; m++) {
        float s0 = 0.f, s1 = 0.f;
#pragma unroll
        for (int n = 0; n < 8; n++) {
            s0 += acc[m][n][0] + acc[m][n][1];
            s1 += acc[m][n][2] + acc[m][n][3];
        }
        rs[m][0] = s0; rs[m][1] = s1;
    }
#pragma unroll
    for (int o = 1; o <= 2; o <<= 1) {
#pragma unroll
        for (int m = 0; m < 2; m++) {
            rs[m][0] += __shfl_xor_sync(0xffffffffu, rs[m][0], o);
            rs[m][1] += __shfl_xor_sync(0xffffffffu, rs[m][1], o);
        }
    }
    if (lt == 0) {
#pragma unroll
        for (int m = 0; m < 2; m++) {
            sh_s0[mbase + m * 16 + lg][warp_n] = rs[m][0];
            sh_s0[mbase + m * 16 + lg + 8][warp_n] = rs[m][1];
        }
    }
    __syncthreads();

    float mu[2][2];
#pragma unroll
    for (int m = 0; m < 2; m++) {
        int r0 = mbase + m * 16 + lg;
        mu[m][0] = (sh_s0[r0][0] + sh_s0[r0][1]) * (1.f / DIM);
        mu[m][1] = (sh_s0[r0 + 8][0] + sh_s0[r0 + 8][1]) * (1.f / DIM);
    }

    float qs[2][2];
#pragma unroll
    for (int m = 0; m < 2; m++) {
        float q0 = 0.f, q1 = 0.f;
#pragma unroll
        for (int n = 0; n < 8; n++) {
            float d;
            d = acc[m][n][0] - mu[m][0]; q0 += d * d;
            d = acc[m][n][1] - mu[m][0]; q0 += d * d;
            d = acc[m][n][2] - mu[m][1]; q1 += d * d;
            d = acc[m][n][3] - mu[m][1]; q1 += d * d;
        }
        qs[m][0] = q0; qs[m][1] = q1;
    }
#pragma unroll
    for (int o = 1; o <= 2; o <<= 1) {
#pragma unroll
        for (int m = 0; m < 2; m++) {
            qs[m][0] += __shfl_xor_sync(0xffffffffu, qs[m][0], o);
            qs[m][1] += __shfl_xor_sync(0xffffffffu, qs[m][1], o);
        }
    }
    if (lt == 0) {
#pragma unroll
        for (int m = 0; m < 2; m++) {
            sh_s1[mbase + m * 16 + lg][warp_n] = qs[m][0];
            sh_s1[mbase + m * 16 + lg + 8][warp_n] = qs[m][1];
        }
    }
    __syncthreads();

    float rstd[2][2];
#pragma unroll
    for (int m = 0; m < 2; m++) {
        int r0 = mbase + m * 16 + lg;
        rstd[m][0] = rsqrtf((sh_s1[r0][0] + sh_s1[r0][1]) * (1.f / DIM) + LN_EPS);
        rstd[m][1] = rsqrtf((sh_s1[r0 + 8][0] + sh_s1[r0 + 8][1]) * (1.f / DIM) + LN_EPS);
    }

    if (MODE == 0) {
        float* xf = (float*)g_x;
#pragma unroll
        for (int m = 0; m < 2; m++) {
            int r0 = mbase + m * 16 + lg;
#pragma unroll
            for (int h = 0; h < 2; h++) {
                int gr = rowBase + r0 + h * 8;
                if (gr < N_NODES) {
#pragma unroll
                    for (int n = 0; n < 8; n++) {
                        int col = nbase + n * 8 + 2 * lt;
                        float v0 = (acc[m][n][h * 2 + 0] - mu[m][h]) * rstd[m][h] * sh_g[col] + sh_be[col];
                        float v1 = (acc[m][n][h * 2 + 1] - mu[m][h]) * rstd[m][h] * sh_g[col + 1] + sh_be[col + 1];
                        v0 = v0 > 0.f ? v0 : LEAKY * v0;
                        v1 = v1 > 0.f ? v1 : LEAKY * v1;
                        float2 p = { v0, v1 };
                        *(float2*)(xf + (size_t)gr * DIM + col) = p;
                    }
                }
            }
        }
    } else {
        __syncthreads();   // reuse sh_s0/sh_s1
        float p0[2][2], p1[2][2];
#pragma unroll
        for (int m = 0; m < 2; m++)
#pragma unroll
            for (int h = 0; h < 2; h++) { p0[m][h] = 0.f; p1[m][h] = 0.f; }
#pragma unroll
        for (int m = 0; m < 2; m++)
#pragma unroll
            for (int n = 0; n < 8; n++) {
                int col = nbase + n * 8 + 2 * lt;
#pragma unroll
                for (int h = 0; h < 2; h++) {
                    float v0 = (acc[m][n][h * 2 + 0] - mu[m][h]) * rstd[m][h] * sh_g[col] + sh_be[col];
                    float v1 = (acc[m][n][h * 2 + 1] - mu[m][h]) * rstd[m][h] * sh_g[col + 1] + sh_be[col + 1];
                    v0 = v0 > 0.f ? v0 : LEAKY * v0;
                    v1 = v1 > 0.f ? v1 : LEAKY * v1;
                    p0[m][h] += v0 * sh_w3[col * 2 + 0] + v1 * sh_w3[(col + 1) * 2 + 0];
                    p1[m][h] += v0 * sh_w3[col * 2 + 1] + v1 * sh_w3[(col + 1) * 2 + 1];
                }
            }
#pragma unroll
        for (int o = 1; o <= 2; o <<= 1) {
#pragma unroll
            for (int m = 0; m < 2; m++)
#pragma unroll
                for (int h = 0; h < 2; h++) {
                    p0[m][h] += __shfl_xor_sync(0xffffffffu, p0[m][h], o);
                    p1[m][h] += __shfl_xor_sync(0xffffffffu, p1[m][h], o);
                }
        }
        if (lt == 0) {
#pragma unroll
            for (int m = 0; m < 2; m++)
#pragma unroll
                for (int h = 0; h < 2; h++) {
                    sh_s0[mbase + m * 16 + lg + h * 8][warp_n] = p0[m][h];
                    sh_s1[mbase + m * 16 + lg + h * 8][warp_n] = p1[m][h];
                }
        }
        __syncthreads();
        if (tid < 128) {
            int gr = rowBase + tid;
            if (gr < N_NODES) {
                float no = g_norm_out[gr];
                float2 p = { no * (sh_s0[tid][0] + sh_s0[tid][1]),
                             no * (sh_s1[tid][0] + sh_s1[tid][1]) };
                g_proj[gr] = p;
            }
        }
    }
}

// ---------------- final aggregation over 2-dim projected features ----------------
__global__ void agg2_kernel(const float* __restrict__ b3, float* __restrict__ out) {
    int node = blockIdx.x * blockDim.x + threadIdx.x;
    if (node >= N_NODES) return;
    int beg = g_row_start[node];
    int end = g_row_start[node + 1];
    float a0 = 0.f, a1 = 0.f;
#pragma unroll 4
    for (int e = beg; e < end; e++) {
        float2 p = g_proj[g_col[e]];
        a0 += p.x;
        a1 += p.y;
    }
    float ni = g_norm_in[node];
    out[node * 2 + 0] = ni * a0 + b3[0];
    out[node * 2 + 1] = ni * a1 + b3[1];
}

// ---------------- launch: pure kernel launches, no host refs to device symbols ------
extern "C" void kernel_launch(void* const* d_in, const int* in_sizes, int n_in,
                              void* d_out, int out_size) {
    const float* feat = (const float*)d_in[0];
    const int*   src  = (const int*)d_in[1];   // int32 (JAX x64 disabled)
    const int*   dst  = (const int*)d_in[2];
    const float* W1  = (const float*)d_in[3];
    const float* b1  = (const float*)d_in[4];
    const float* W2  = (const float*)d_in[5];
    const float* b2  = (const float*)d_in[6];
    const float* W3  = (const float*)d_in[7];
    const float* b3  = (const float*)d_in[8];
    const float* g1  = (const float*)d_in[9];
    const float* be1 = (const float*)d_in[10];
    const float* g2  = (const float*)d_in[11];
    const float* be2 = (const float*)d_in[12];
    float* out = (float*)d_out;

    const int NB_N  = (N_NODES + 255) / 256;
    const int NB_E8 = (N_EDGES / 8 + 255) / 256;
    const int NB_E4 = (N_EDGES / 4 + 255) / 256;
    const int NB_W  = (N_NODES + 7) / 8;
    const int NB_G  = (N_NODES + 127) / 128;   // 391

    // graph structure (+ W pre-split fused into the single-block scan)
    zero_deg_kernel<<<NB_N, 256>>>();
    count_deg_kernel<<<NB_E8, 256>>>((const int4*)src, (const int4*)dst);
    scan_bsum_kernel<<<N_SBLK, SCAN_BLK>>>();
    scan_partials_split_kernel<<<129, 256>>>(W1, W2);
    scan_final_kernel<<<N_SBLK, SCAN_BLK>>>();
    fill_csr_kernel<<<NB_E4, 256>>>((const int4*)src, (const int4*)dst);

    // layer 1: agg -> tf32 mma gemm + bias + LN + leaky -> g_x
    agg128_kernel<false><<<NB_W, 256>>>(feat);
    gemm_mma_kernel<0, 0><<<NB_G, 256>>>(b1, g1, be1, nullptr);

    // layer 2: agg -> tf32 mma gemm + bias + LN + leaky + W3 projection -> g_proj
    agg128_kernel<true><<<NB_W, 256>>>(feat);
    gemm_mma_kernel<1, 1><<<NB_G, 256>>>(b2, g2, be2, W3);

    // layer 3 aggregation
    agg2_kernel<<<NB_N, 256>>>(b3, out);
}

// round 14
// speedup vs baseline: 1.3394x; 1.0181x over previous
#include <cuda_runtime.h>
#include <cuda_bf16.h>
#include <cuda_fp16.h>
#include <stdint.h>

#define N_NODES 50000
#define N_EDGES 800000
#define DIM 128
#define VDIM 32            // DIM/4 float4 per row
#define LEAKY 0.01f
#define LN_EPS 1e-5f

#define SCAN_BLK 256
#define N_SBLK ((N_NODES + SCAN_BLK - 1) / SCAN_BLK)   // 196

// ---------------- scratch (device globals; allocation is forbidden) ----------------
__device__ int    g_deg_in[N_NODES];
__device__ int    g_deg_out[N_NODES];
__device__ float  g_norm_in[N_NODES];
__device__ float  g_norm_out[N_NODES];
__device__ int    g_row_start[N_NODES + 1];
__device__ int    g_col[N_EDGES];
__device__ int4   g_rank4[N_EDGES / 4];            // per-edge rank within dst bucket
__device__ int    g_bsum[N_SBLK];

__device__ float4 g_agg[(size_t)N_NODES * VDIM];   // aggregation output (fp32)
__device__ uint4  g_fh[(size_t)N_NODES * 16];      // features in fp16 (128 halves/row)
__device__ uint4  g_xh[(size_t)N_NODES * 16];      // post LN+leaky features (fp16)
__device__ float2 g_proj[N_NODES];                 // layer-3 projected features
__device__ uint2  g_w2a[128 * 128];                // W1 pre-split (hi,lo) tf32
__device__ uint2  g_w2b[128 * 128];                // W2 pre-split

__device__ __forceinline__ int clamp_idx(int v) {
    v = v < 0 ? 0 : v;
    return v >= N_NODES ? N_NODES - 1 : v;
}

// ---------------- tf32 mma helpers (base PTX, plain sm_100-safe) ----------------
__device__ __forceinline__ uint32_t cvt_tf32(float f) {
    uint32_t r;
    asm("cvt.rna.tf32.f32 %0, %1;" : "=r"(r) : "f"(f));
    return r;
}
__device__ __forceinline__ void mma8(float* c, const uint32_t* a, uint32_t b0, uint32_t b1) {
    asm volatile(
        "mma.sync.aligned.m16n8k8.row.col.f32.tf32.tf32.f32 "
        "{%0,%1,%2,%3}, {%4,%5,%6,%7}, {%8,%9}, {%0,%1,%2,%3};"
        : "+f"(c[0]), "+f"(c[1]), "+f"(c[2]), "+f"(c[3])
        : "r"(a[0]), "r"(a[1]), "r"(a[2]), "r"(a[3]), "r"(b0), "r"(b1));
}

// ---------------- setup ----------------
__global__ void zero_deg_kernel() {
    int i = blockIdx.x * blockDim.x + threadIdx.x;
    if (i < N_NODES) { g_deg_in[i] = 0; g_deg_out[i] = 0; }
}

// fp32 features -> fp16 (8 elems/thread)
__global__ void feat_to_h_kernel(const float4* __restrict__ feat4) {
    int t = blockIdx.x * blockDim.x + threadIdx.x;
    if (t >= N_NODES * 16) return;
    float4 a = feat4[t * 2];
    float4 b = feat4[t * 2 + 1];
    __half2 h0 = __floats2half2_rn(a.x, a.y);
    __half2 h1 = __floats2half2_rn(a.z, a.w);
    __half2 h2 = __floats2half2_rn(b.x, b.y);
    __half2 h3 = __floats2half2_rn(b.z, b.w);
    uint4 o = { *(uint32_t*)&h0, *(uint32_t*)&h1, *(uint32_t*)&h2, *(uint32_t*)&h3 };
    g_fh[t] = o;
}

// 8 edges per thread; rank (position within dst bucket) = atomicAdd return, stored coalesced
__global__ void count_deg_kernel(const int4* __restrict__ src4,
                                 const int4* __restrict__ dst4) {
    int t = blockIdx.x * blockDim.x + threadIdx.x;
    if (t >= N_EDGES / 8) return;
    int4 s0 = src4[t * 2], s1 = src4[t * 2 + 1];
    int4 d0 = dst4[t * 2], d1 = dst4[t * 2 + 1];
    atomicAdd(&g_deg_out[clamp_idx(s0.x)], 1);
    atomicAdd(&g_deg_out[clamp_idx(s0.y)], 1);
    atomicAdd(&g_deg_out[clamp_idx(s0.z)], 1);
    atomicAdd(&g_deg_out[clamp_idx(s0.w)], 1);
    atomicAdd(&g_deg_out[clamp_idx(s1.x)], 1);
    atomicAdd(&g_deg_out[clamp_idx(s1.y)], 1);
    atomicAdd(&g_deg_out[clamp_idx(s1.z)], 1);
    atomicAdd(&g_deg_out[clamp_idx(s1.w)], 1);
    int4 r0, r1;
    r0.x = atomicAdd(&g_deg_in[clamp_idx(d0.x)], 1);
    r0.y = atomicAdd(&g_deg_in[clamp_idx(d0.y)], 1);
    r0.z = atomicAdd(&g_deg_in[clamp_idx(d0.z)], 1);
    r0.w = atomicAdd(&g_deg_in[clamp_idx(d0.w)], 1);
    r1.x = atomicAdd(&g_deg_in[clamp_idx(d1.x)], 1);
    r1.y = atomicAdd(&g_deg_in[clamp_idx(d1.y)], 1);
    r1.z = atomicAdd(&g_deg_in[clamp_idx(d1.z)], 1);
    r1.w = atomicAdd(&g_deg_in[clamp_idx(d1.w)], 1);
    g_rank4[t * 2]     = r0;
    g_rank4[t * 2 + 1] = r1;
}

__global__ __launch_bounds__(SCAN_BLK)
void scan_bsum_kernel() {
    int i = blockIdx.x * SCAN_BLK + threadIdx.x;
    int v = (i < N_NODES) ? g_deg_in[i] : 0;
#pragma unroll
    for (int o = 16; o; o >>= 1) v += __shfl_xor_sync(0xffffffffu, v, o);
    __shared__ int wsum[SCAN_BLK / 32];
    if ((threadIdx.x & 31) == 0) wsum[threadIdx.x >> 5] = v;
    __syncthreads();
    if (threadIdx.x == 0) {
        int s = 0;
#pragma unroll
        for (int w = 0; w < SCAN_BLK / 32; w++) s += wsum[w];
        g_bsum[blockIdx.x] = s;
    }
}

// block 0: exclusive scan of the 196 partials.  blocks 1..128: W1/W2 tf32 pre-split.
__global__ __launch_bounds__(256)
void scan_partials_split_kernel(const float* __restrict__ W1,
                                const float* __restrict__ W2) {
    if (blockIdx.x == 0) {
        __shared__ int wsum[8];
        __shared__ int woff[8];
        int tid = threadIdx.x;
        int lane = tid & 31, wid = tid >> 5;
        int v = (tid < N_SBLK) ? g_bsum[tid] : 0;
        int incl = v;
#pragma unroll
        for (int o = 1; o < 32; o <<= 1) {
            int t = __shfl_up_sync(0xffffffffu, incl, o);
            if (lane >= o) incl += t;
        }
        if (lane == 31) wsum[wid] = incl;
        __syncthreads();
        if (wid == 0 && lane < 8) {
            int w = wsum[lane];
            int wi = w;
#pragma unroll
            for (int o = 1; o < 8; o <<= 1) {
                int t = __shfl_up_sync(0xffu, wi, o);
                if (lane >= o) wi += t;
            }
            woff[lane] = wi - w;
            if (lane == 7) g_row_start[N_NODES] = wi;   // total edge count
        }
        __syncthreads();
        if (tid < N_SBLK) g_bsum[tid] = woff[wid] + incl - v;   // exclusive prefix
    } else {
        int bi = blockIdx.x - 1;                 // 0..127
        const float* W = (bi < 64) ? W1 : W2;
        uint2* out = (bi < 64) ? g_w2a : g_w2b;
        int t = (bi & 63) * 256 + threadIdx.x;   // 0..16383
        float w = W[t];
        uint32_t hi = cvt_tf32(w);
        uint32_t lo = cvt_tf32(w - __uint_as_float(hi));
        uint2 p = { hi, lo };
        out[t] = p;
    }
}

__global__ __launch_bounds__(SCAN_BLK)
void scan_final_kernel() {
    int tid = threadIdx.x;
    int i = blockIdx.x * SCAN_BLK + tid;
    int lane = tid & 31, wid = tid >> 5;
    int v = (i < N_NODES) ? g_deg_in[i] : 0;
    int incl = v;
#pragma unroll
    for (int o = 1; o < 32; o <<= 1) {
        int t = __shfl_up_sync(0xffffffffu, incl, o);
        if (lane >= o) incl += t;
    }
    __shared__ int wsum[SCAN_BLK / 32];
    __shared__ int woff[SCAN_BLK / 32];
    if (lane == 31) wsum[wid] = incl;
    __syncthreads();
    if (tid == 0) {
        int s = 0;
#pragma unroll
        for (int w = 0; w < SCAN_BLK / 32; w++) { woff[w] = s; s += wsum[w]; }
    }
    __syncthreads();
    if (i < N_NODES) {
        int excl = incl - v + woff[wid] + g_bsum[blockIdx.x];
        g_row_start[i] = excl;
        g_norm_out[i] = rsqrtf(fmaxf((float)g_deg_out[i], 1.0f));
        g_norm_in[i]  = rsqrtf(fmaxf((float)v, 1.0f));
    }
}

// atomic-free CSR fill using precomputed ranks
__global__ void fill_csr_kernel(const int4* __restrict__ src4,
                                const int4* __restrict__ dst4) {
    int t = blockIdx.x * blockDim.x + threadIdx.x;
    if (t >= N_EDGES / 4) return;
    int4 s = src4[t];
    int4 d = dst4[t];
    int4 r = g_rank4[t];
    g_col[g_row_start[clamp_idx(d.x)] + r.x] = clamp_idx(s.x);
    g_col[g_row_start[clamp_idx(d.y)] + r.y] = clamp_idx(s.y);
    g_col[g_row_start[clamp_idx(d.z)] + r.z] = clamp_idx(s.z);
    g_col[g_row_start[clamp_idx(d.w)] + r.w] = clamp_idx(s.w);
}

// ---------------- aggregation: warp per node, fp16 rows (256B), fp32 accumulate -------
// USE_GX=false: read g_fh (converted input feats). true: read g_xh (layer-1 output).
template <bool USE_GX>
__global__ __launch_bounds__(256)
void agg128_kernel() {
    int node = blockIdx.x * (blockDim.x >> 5) + (threadIdx.x >> 5);
    if (node >= N_NODES) return;
    int lane = threadIdx.x & 31;
    int beg = g_row_start[node];
    int end = g_row_start[node + 1];
    const uint2* __restrict__ xs = USE_GX ? (const uint2*)g_xh : (const uint2*)g_fh;
    float ax = 0.f, ay = 0.f, az = 0.f, aw = 0.f;
#pragma unroll 8
    for (int e = beg; e < end; e++) {
        int c = g_col[e];
        float w = g_norm_out[c];
        uint2 hv = xs[(size_t)c * 32 + lane];       // 4 halves
        float2 f0 = __half22float2(*(__half2*)&hv.x);
        float2 f1 = __half22float2(*(__half2*)&hv.y);
        ax = fmaf(w, f0.x, ax);
        ay = fmaf(w, f0.y, ay);
        az = fmaf(w, f1.x, az);
        aw = fmaf(w, f1.y, aw);
    }
    float ni = g_norm_in[node];
    float4 o = { ax * ni, ay * ni, az * ni, aw * ni };
    g_agg[(size_t)node * VDIM + lane] = o;
}

// pack two fp32 into (hi,lo)(hi,lo) tf32 uint4 — pure scalar, no local arrays
__device__ __forceinline__ uint4 pack2_tf32(float x, float y) {
    uint32_t hx = cvt_tf32(x);
    uint32_t hy = cvt_tf32(y);
    uint4 p;
    p.x = hx; p.y = cvt_tf32(x - __uint_as_float(hx));
    p.z = hy; p.w = cvt_tf32(y - __uint_as_float(hy));
    return p;
}

// ---------------- tf32 mma GEMM + bias + LN + leaky (+ W3 projection) -----------------
// Block tile 128x128, K=128 in 8 chunks of 16. 8 warps: 4 along M, 2 along N.
// MODE 0 -> g_xh (fp16). MODE 1 -> g_proj (W3 projection with norm_out).
#define AP2 20     // A pitch in uint2
#define BP2 132    // B pitch in uint2
template <int MODE, int WSEL>
__global__ __launch_bounds__(256)
void gemm_mma_kernel(const float* __restrict__ b,
                     const float* __restrict__ g, const float* __restrict__ be,
                     const float* __restrict__ W3) {
    __shared__ uint2 As[128][AP2];                 // 20 KB   (k index 0..15)
    __shared__ uint2 Bs[16][BP2];                  // 16.9 KB (col 0..127)
    __shared__ float sh_b[128], sh_g[128], sh_be[128], sh_w3[256];
    __shared__ float sh_s0[128][2], sh_s1[128][2];

    const uint2* __restrict__ W2 = (WSEL == 0) ? g_w2a : g_w2b;

    int tid = threadIdx.x;
    int wid = tid >> 5, lane = tid & 31;
    int lg = lane >> 2, lt = lane & 3;
    int warp_m = wid & 3, warp_n = wid >> 2;
    int mbase = warp_m * 32, nbase = warp_n * 64;
    int rowBase = blockIdx.x * 128;

    if (tid < 128) { sh_b[tid] = b[tid]; sh_g[tid] = g[tid]; sh_be[tid] = be[tid]; }
    if (MODE == 1 && tid >= 128) {
        sh_w3[2 * (tid - 128)] = W3[2 * (tid - 128)];
        sh_w3[2 * (tid - 128) + 1] = W3[2 * (tid - 128) + 1];
    }

    float acc[2][8][4];
#pragma unroll
    for (int m = 0; m < 2; m++)
#pragma unroll
        for (int n = 0; n < 8; n++)
#pragma unroll
            for (int e = 0; e < 4; e++) acc[m][n][e] = 0.f;

    const float* Af = (const float*)g_agg;
    int a_row = tid >> 1;                 // staging: 2 threads per A row
    int a_half = tid & 1;                 // k-half (8 elems)
    int b_k = tid >> 4;                   // staging: 16 threads per B row
    int b_j = tid & 15;                   // uint4 group

    for (int kc = 0; kc < 8; kc++) {
        // ---- stage A chunk 128x16: LDG128 x2, scalar split, 4x STS128 ----
        {
            int gr = rowBase + a_row;
            float4 v0 = make_float4(0.f, 0.f, 0.f, 0.f), v1 = v0;
            if (gr < N_NODES) {
                const float* p = Af + (size_t)gr * DIM + kc * 16 + a_half * 8;
                v0 = *(const float4*)p;
                v1 = *(const float4*)(p + 4);
            }
            uint4* dst = (uint4*)&As[a_row][a_half * 8];
            dst[0] = pack2_tf32(v0.x, v0.y);
            dst[1] = pack2_tf32(v0.z, v0.w);
            dst[2] = pack2_tf32(v1.x, v1.y);
            dst[3] = pack2_tf32(v1.z, v1.w);
        }
        // ---- stage B chunk 16x128: pure uint4 copy from pre-split table ----
        {
            const uint4* srcw = (const uint4*)(W2 + (size_t)(kc * 16 + b_k) * 128);
            uint4* dstw = (uint4*)&Bs[b_k][0];
#pragma unroll
            for (int r = 0; r < 4; r++) dstw[b_j + r * 16] = srcw[b_j + r * 16];
        }
        __syncthreads();

#pragma unroll
        for (int ks = 0; ks < 2; ks++) {
            int kb = ks * 8;
            uint32_t a_hi[2][4], a_lo[2][4];
#pragma unroll
            for (int m = 0; m < 2; m++) {
                int r0 = mbase + m * 16 + lg;
                uint2 p0 = As[r0][kb + lt];
                uint2 p1 = As[r0 + 8][kb + lt];
                uint2 p2 = As[r0][kb + lt + 4];
                uint2 p3 = As[r0 + 8][kb + lt + 4];
                a_hi[m][0] = p0.x; a_lo[m][0] = p0.y;
                a_hi[m][1] = p1.x; a_lo[m][1] = p1.y;
                a_hi[m][2] = p2.x; a_lo[m][2] = p2.y;
                a_hi[m][3] = p3.x; a_lo[m][3] = p3.y;
            }
#pragma unroll
            for (int n = 0; n < 8; n++) {
                int c0 = nbase + n * 8 + lg;
                uint2 q0 = Bs[kb + lt][c0];
                uint2 q1 = Bs[kb + lt + 4][c0];
#pragma unroll
                for (int m = 0; m < 2; m++) {
                    mma8(acc[m][n], a_hi[m], q0.x, q1.x);   // hi*hi
                    mma8(acc[m][n], a_hi[m], q0.y, q1.y);   // hi*lo
                    mma8(acc[m][n], a_lo[m], q0.x, q1.x);   // lo*hi
                }
            }
        }
        __syncthreads();
    }

    // ---- epilogue: bias, LN stats via shfl + cross-warp SMEM, leaky, output ----
#pragma unroll
    for (int m = 0; m < 2; m++)
#pragma unroll
        for (int n = 0; n < 8; n++) {
            int col = nbase + n * 8 + 2 * lt;
            acc[m][n][0] += sh_b[col];
            acc[m][n][1] += sh_b[col + 1];
            acc[m][n][2] += sh_b[col];
            acc[m][n][3] += sh_b[col + 1];
        }

    float rs[2][2];
#pragma unroll
    for (int m = 0; m < 2; m++) {
        float s0 = 0.f, s1 = 0.f;
#pragma unroll
        for (int n = 0; n < 8; n++) {
            s0 += acc[m][n][0] + acc[m][n][1];
            s1 += acc[m][n][2] + acc[m][n][3];
        }
        rs[m][0] = s0; rs[m][1] = s1;
    }
#pragma unroll
    for (int o = 1; o <= 2; o <<= 1) {
#pragma unroll
        for (int m = 0; m < 2; m++) {
            rs[m][0] += __shfl_xor_sync(0xffffffffu, rs[m][0], o);
            rs[m][1] += __shfl_xor_sync(0xffffffffu, rs[m][1], o);
        }
    }
    if (lt == 0) {
#pragma unroll
        for (int m = 0; m < 2; m++) {
            sh_s0[mbase + m * 16 + lg][warp_n] = rs[m][0];
            sh_s0[mbase + m * 16 + lg + 8][warp_n] = rs[m][1];
        }
    }
    __syncthreads();

    float mu[2][2];
#pragma unroll
    for (int m = 0; m < 2; m++) {
        int r0 = mbase + m * 16 + lg;
        mu[m][0] = (sh_s0[r0][0] + sh_s0[r0][1]) * (1.f / DIM);
        mu[m][1] = (sh_s0[r0 + 8][0] + sh_s0[r0 + 8][1]) * (1.f / DIM);
    }

    float qs[2][2];
#pragma unroll
    for (int m = 0; m < 2; m++) {
        float q0 = 0.f, q1 = 0.f;
#pragma unroll
        for (int n = 0; n < 8; n++) {
            float d;
            d = acc[m][n][0] - mu[m][0]; q0 += d * d;
            d = acc[m][n][1] - mu[m][0]; q0 += d * d;
            d = acc[m][n][2] - mu[m][1]; q1 += d * d;
            d = acc[m][n][3] - mu[m][1]; q1 += d * d;
        }
        qs[m][0] = q0; qs[m][1] = q1;
    }
#pragma unroll
    for (int o = 1; o <= 2; o <<= 1) {
#pragma unroll
        for (int m = 0; m < 2; m++) {
            qs[m][0] += __shfl_xor_sync(0xffffffffu, qs[m][0], o);
            qs[m][1] += __shfl_xor_sync(0xffffffffu, qs[m][1], o);
        }
    }
    if (lt == 0) {
#pragma unroll
        for (int m = 0; m < 2; m++) {
            sh_s1[mbase + m * 16 + lg][warp_n] = qs[m][0];
            sh_s1[mbase + m * 16 + lg + 8][warp_n] = qs[m][1];
        }
    }
    __syncthreads();

    float rstd[2][2];
#pragma unroll
    for (int m = 0; m < 2; m++) {
        int r0 = mbase + m * 16 + lg;
        rstd[m][0] = rsqrtf((sh_s1[r0][0] + sh_s1[r0][1]) * (1.f / DIM) + LN_EPS);
        rstd[m][1] = rsqrtf((sh_s1[r0 + 8][0] + sh_s1[r0 + 8][1]) * (1.f / DIM) + LN_EPS);
    }

    if (MODE == 0) {
        __half* xh = (__half*)g_xh;
#pragma unroll
        for (int m = 0; m < 2; m++) {
            int r0 = mbase + m * 16 + lg;
#pragma unroll
            for (int h = 0; h < 2; h++) {
                int gr = rowBase + r0 + h * 8;
                if (gr < N_NODES) {
#pragma unroll
                    for (int n = 0; n < 8; n++) {
                        int col = nbase + n * 8 + 2 * lt;
                        float v0 = (acc[m][n][h * 2 + 0] - mu[m][h]) * rstd[m][h] * sh_g[col] + sh_be[col];
                        float v1 = (acc[m][n][h * 2 + 1] - mu[m][h]) * rstd[m][h] * sh_g[col + 1] + sh_be[col + 1];
                        v0 = v0 > 0.f ? v0 : LEAKY * v0;
                        v1 = v1 > 0.f ? v1 : LEAKY * v1;
                        __half2 hp = __floats2half2_rn(v0, v1);
                        *(__half2*)(xh + (size_t)gr * DIM + col) = hp;
                    }
                }
            }
        }
    } else {
        __syncthreads();   // reuse sh_s0/sh_s1
        float p0[2][2], p1[2][2];
#pragma unroll
        for (int m = 0; m < 2; m++)
#pragma unroll
            for (int h = 0; h < 2; h++) { p0[m][h] = 0.f; p1[m][h] = 0.f; }
#pragma unroll
        for (int m = 0; m < 2; m++)
#pragma unroll
            for (int n = 0; n < 8; n++) {
                int col = nbase + n * 8 + 2 * lt;
#pragma unroll
                for (int h = 0; h < 2; h++) {
                    float v0 = (acc[m][n][h * 2 + 0] - mu[m][h]) * rstd[m][h] * sh_g[col] + sh_be[col];
                    float v1 = (acc[m][n][h * 2 + 1] - mu[m][h]) * rstd[m][h] * sh_g[col + 1] + sh_be[col + 1];
                    v0 = v0 > 0.f ? v0 : LEAKY * v0;
                    v1 = v1 > 0.f ? v1 : LEAKY * v1;
                    p0[m][h] += v0 * sh_w3[col * 2 + 0] + v1 * sh_w3[(col + 1) * 2 + 0];
                    p1[m][h] += v0 * sh_w3[col * 2 + 1] + v1 * sh_w3[(col + 1) * 2 + 1];
                }
            }
#pragma unroll
        for (int o = 1; o <= 2; o <<= 1) {
#pragma unroll
            for (int m = 0; m < 2; m++)
#pragma unroll
                for (int h = 0; h < 2; h++) {
                    p0[m][h] += __shfl_xor_sync(0xffffffffu, p0[m][h], o);
                    p1[m][h] += __shfl_xor_sync(0xffffffffu, p1[m][h], o);
                }
        }
        if (lt == 0) {
#pragma unroll
            for (int m = 0; m < 2; m++)
#pragma unroll
                for (int h = 0; h < 2; h++) {
                    sh_s0[mbase + m * 16 + lg + h * 8][warp_n] = p0[m][h];
                    sh_s1[mbase + m * 16 + lg + h * 8][warp_n] = p1[m][h];
                }
        }
        __syncthreads();
        if (tid < 128) {
            int gr = rowBase + tid;
            if (gr < N_NODES) {
                float no = g_norm_out[gr];
                float2 p = { no * (sh_s0[tid][0] + sh_s0[tid][1]),
                             no * (sh_s1[tid][0] + sh_s1[tid][1]) };
                g_proj[gr] = p;
            }
        }
    }
}

// ---------------- final aggregation over 2-dim projected features ----------------
__global__ void agg2_kernel(const float* __restrict__ b3, float* __restrict__ out) {
    int node = blockIdx.x * blockDim.x + threadIdx.x;
    if (node >= N_NODES) return;
    int beg = g_row_start[node];
    int end = g_row_start[node + 1];
    float a0 = 0.f, a1 = 0.f;
#pragma unroll 4
    for (int e = beg; e < end; e++) {
        float2 p = g_proj[g_col[e]];
        a0 += p.x;
        a1 += p.y;
    }
    float ni = g_norm_in[node];
    out[node * 2 + 0] = ni * a0 + b3[0];
    out[node * 2 + 1] = ni * a1 + b3[1];
}

// ---------------- launch: pure kernel launches, no host refs to device symbols ------
extern "C" void kernel_launch(void* const* d_in, const int* in_sizes, int n_in,
                              void* d_out, int out_size) {
    const float* feat = (const float*)d_in[0];
    const int*   src  = (const int*)d_in[1];   // int32 (JAX x64 disabled)
    const int*   dst  = (const int*)d_in[2];
    const float* W1  = (const float*)d_in[3];
    const float* b1  = (const float*)d_in[4];
    const float* W2  = (const float*)d_in[5];
    const float* b2  = (const float*)d_in[6];
    const float* W3  = (const float*)d_in[7];
    const float* b3  = (const float*)d_in[8];
    const float* g1  = (const float*)d_in[9];
    const float* be1 = (const float*)d_in[10];
    const float* g2  = (const float*)d_in[11];
    const float* be2 = (const float*)d_in[12];
    float* out = (float*)d_out;

    const int NB_N  = (N_NODES + 255) / 256;
    const int NB_E8 = (N_EDGES / 8 + 255) / 256;
    const int NB_E4 = (N_EDGES / 4 + 255) / 256;
    const int NB_W  = (N_NODES + 7) / 8;
    const int NB_G  = (N_NODES + 127) / 128;   // 391
    const int NB_F  = (N_NODES * 16 + 255) / 256;

    // graph structure (+ feat fp16 convert + W pre-split fused into the scan phase)
    zero_deg_kernel<<<NB_N, 256>>>();
    feat_to_h_kernel<<<NB_F, 256>>>((const float4*)feat);
    count_deg_kernel<<<NB_E8, 256>>>((const int4*)src, (const int4*)dst);
    scan_bsum_kernel<<<N_SBLK, SCAN_BLK>>>();
    scan_partials_split_kernel<<<129, 256>>>(W1, W2);
    scan_final_kernel<<<N_SBLK, SCAN_BLK>>>();
    fill_csr_kernel<<<NB_E4, 256>>>((const int4*)src, (const int4*)dst);

    // layer 1: agg (fp16 gather) -> tf32 mma gemm + bias + LN + leaky -> g_xh (fp16)
    agg128_kernel<false><<<NB_W, 256>>>();
    gemm_mma_kernel<0, 0><<<NB_G, 256>>>(b1, g1, be1, nullptr);

    // layer 2: agg (fp16 gather) -> tf32 mma gemm + ... + W3 projection -> g_proj
    agg128_kernel<true><<<NB_W, 256>>>();
    gemm_mma_kernel<1, 1><<<NB_G, 256>>>(b2, g2, be2, W3);

    // layer 3 aggregation
    agg2_kernel<<<NB_N, 256>>>(b3, out);
}

// round 15
// speedup vs baseline: 1.3558x; 1.0123x over previous
#include <cuda_runtime.h>
#include <cuda_bf16.h>
#include <cuda_fp16.h>
#include <stdint.h>

#define N_NODES 50000
#define N_EDGES 800000
#define DIM 128
#define VDIM 32            // DIM/4 float4 per row
#define LEAKY 0.01f
#define LN_EPS 1e-5f

#define SCAN_BLK 256
#define N_SBLK ((N_NODES + SCAN_BLK - 1) / SCAN_BLK)   // 196

// ---------------- scratch (device globals; allocation is forbidden) ----------------
__device__ int    g_deg_in[N_NODES];
__device__ int    g_deg_out[N_NODES];
__device__ float  g_norm_in[N_NODES];
__device__ float  g_norm_out[N_NODES];
__device__ int    g_beg[N_NODES];                  // bucket start (atomic-allocated)
__device__ int    g_cursor;
__device__ int    g_col[N_EDGES];
__device__ int4   g_rank4[N_EDGES / 4];            // per-edge rank within dst bucket

__device__ float4 g_agg[(size_t)N_NODES * VDIM];   // aggregation output (fp32)
__device__ uint4  g_fh[(size_t)N_NODES * 16];      // features in fp16 (128 halves/row)
__device__ uint4  g_xh[(size_t)N_NODES * 16];      // post LN+leaky features (fp16)
__device__ float2 g_proj[N_NODES];                 // layer-3 projected features
__device__ uint2  g_w2a[128 * 128];                // W1 pre-split (hi,lo) tf32
__device__ uint2  g_w2b[128 * 128];                // W2 pre-split

__device__ __forceinline__ int clamp_idx(int v) {
    v = v < 0 ? 0 : v;
    return v >= N_NODES ? N_NODES - 1 : v;
}

// ---------------- tf32 mma helpers (base PTX, plain sm_100-safe) ----------------
__device__ __forceinline__ uint32_t cvt_tf32(float f) {
    uint32_t r;
    asm("cvt.rna.tf32.f32 %0, %1;" : "=r"(r) : "f"(f));
    return r;
}
__device__ __forceinline__ void mma8(float* c, const uint32_t* a, uint32_t b0, uint32_t b1) {
    asm volatile(
        "mma.sync.aligned.m16n8k8.row.col.f32.tf32.tf32.f32 "
        "{%0,%1,%2,%3}, {%4,%5,%6,%7}, {%8,%9}, {%0,%1,%2,%3};"
        : "+f"(c[0]), "+f"(c[1]), "+f"(c[2]), "+f"(c[3])
        : "r"(a[0]), "r"(a[1]), "r"(a[2]), "r"(a[3]), "r"(b0), "r"(b1));
}

// ---------------- init: zero degrees + cursor, convert feats to fp16 ----------------
__global__ void init_kernel(const float4* __restrict__ feat4) {
    int t = blockIdx.x * blockDim.x + threadIdx.x;
    if (t == 0) g_cursor = 0;
    if (t < N_NODES) { g_deg_in[t] = 0; g_deg_out[t] = 0; }
    if (t < N_NODES * 16) {
        float4 a = feat4[t * 2];
        float4 b = feat4[t * 2 + 1];
        __half2 h0 = __floats2half2_rn(a.x, a.y);
        __half2 h1 = __floats2half2_rn(a.z, a.w);
        __half2 h2 = __floats2half2_rn(b.x, b.y);
        __half2 h3 = __floats2half2_rn(b.z, b.w);
        uint4 o = { *(uint32_t*)&h0, *(uint32_t*)&h1, *(uint32_t*)&h2, *(uint32_t*)&h3 };
        g_fh[t] = o;
    }
}

// 8 edges per thread; rank (position within dst bucket) = atomicAdd return
__global__ void count_deg_kernel(const int4* __restrict__ src4,
                                 const int4* __restrict__ dst4) {
    int t = blockIdx.x * blockDim.x + threadIdx.x;
    if (t >= N_EDGES / 8) return;
    int4 s0 = src4[t * 2], s1 = src4[t * 2 + 1];
    int4 d0 = dst4[t * 2], d1 = dst4[t * 2 + 1];
    atomicAdd(&g_deg_out[clamp_idx(s0.x)], 1);
    atomicAdd(&g_deg_out[clamp_idx(s0.y)], 1);
    atomicAdd(&g_deg_out[clamp_idx(s0.z)], 1);
    atomicAdd(&g_deg_out[clamp_idx(s0.w)], 1);
    atomicAdd(&g_deg_out[clamp_idx(s1.x)], 1);
    atomicAdd(&g_deg_out[clamp_idx(s1.y)], 1);
    atomicAdd(&g_deg_out[clamp_idx(s1.z)], 1);
    atomicAdd(&g_deg_out[clamp_idx(s1.w)], 1);
    int4 r0, r1;
    r0.x = atomicAdd(&g_deg_in[clamp_idx(d0.x)], 1);
    r0.y = atomicAdd(&g_deg_in[clamp_idx(d0.y)], 1);
    r0.z = atomicAdd(&g_deg_in[clamp_idx(d0.z)], 1);
    r0.w = atomicAdd(&g_deg_in[clamp_idx(d0.w)], 1);
    r1.x = atomicAdd(&g_deg_in[clamp_idx(d1.x)], 1);
    r1.y = atomicAdd(&g_deg_in[clamp_idx(d1.y)], 1);
    r1.z = atomicAdd(&g_deg_in[clamp_idx(d1.z)], 1);
    r1.w = atomicAdd(&g_deg_in[clamp_idx(d1.w)], 1);
    g_rank4[t * 2]     = r0;
    g_rank4[t * 2 + 1] = r1;
}

// blocks [0, N_SBLK): single-pass bucket allocation (block scan + atomic cursor),
// plus norms.  blocks [N_SBLK, N_SBLK+128): W1/W2 tf32 pre-split.
__global__ __launch_bounds__(256)
void alloc_split_kernel(const float* __restrict__ W1, const float* __restrict__ W2) {
    if (blockIdx.x < N_SBLK) {
        __shared__ int wsum[8];
        __shared__ int woff[8];
        __shared__ int base_sh;
        int tid = threadIdx.x;
        int i = blockIdx.x * SCAN_BLK + tid;
        int lane = tid & 31, wid = tid >> 5;
        int v = (i < N_NODES) ? g_deg_in[i] : 0;
        int incl = v;
#pragma unroll
        for (int o = 1; o < 32; o <<= 1) {
            int t = __shfl_up_sync(0xffffffffu, incl, o);
            if (lane >= o) incl += t;
        }
        if (lane == 31) wsum[wid] = incl;
        __syncthreads();
        if (tid == 0) {
            int s = 0;
#pragma unroll
            for (int w = 0; w < 8; w++) { woff[w] = s; s += wsum[w]; }
            base_sh = atomicAdd(&g_cursor, s);
        }
        __syncthreads();
        if (i < N_NODES) {
            g_beg[i] = base_sh + woff[wid] + incl - v;
            g_norm_out[i] = rsqrtf(fmaxf((float)g_deg_out[i], 1.0f));
            g_norm_in[i]  = rsqrtf(fmaxf((float)v, 1.0f));
        }
    } else {
        int bi = blockIdx.x - N_SBLK;            // 0..127
        const float* W = (bi < 64) ? W1 : W2;
        uint2* out = (bi < 64) ? g_w2a : g_w2b;
        int t = (bi & 63) * 256 + threadIdx.x;   // 0..16383
        float w = W[t];
        uint32_t hi = cvt_tf32(w);
        uint32_t lo = cvt_tf32(w - __uint_as_float(hi));
        uint2 p = { hi, lo };
        out[t] = p;
    }
}

// atomic-free CSR fill using precomputed ranks
__global__ void fill_csr_kernel(const int4* __restrict__ src4,
                                const int4* __restrict__ dst4) {
    int t = blockIdx.x * blockDim.x + threadIdx.x;
    if (t >= N_EDGES / 4) return;
    int4 s = src4[t];
    int4 d = dst4[t];
    int4 r = g_rank4[t];
    g_col[g_beg[clamp_idx(d.x)] + r.x] = clamp_idx(s.x);
    g_col[g_beg[clamp_idx(d.y)] + r.y] = clamp_idx(s.y);
    g_col[g_beg[clamp_idx(d.z)] + r.z] = clamp_idx(s.z);
    g_col[g_beg[clamp_idx(d.w)] + r.w] = clamp_idx(s.w);
}

// ---------------- aggregation: warp per node, fp16 rows (256B), fp32 accumulate -------
template <bool USE_GX>
__global__ __launch_bounds__(256)
void agg128_kernel() {
    int node = blockIdx.x * (blockDim.x >> 5) + (threadIdx.x >> 5);
    if (node >= N_NODES) return;
    int lane = threadIdx.x & 31;
    int beg = g_beg[node];
    int end = beg + g_deg_in[node];
    const uint2* __restrict__ xs = USE_GX ? (const uint2*)g_xh : (const uint2*)g_fh;
    float ax = 0.f, ay = 0.f, az = 0.f, aw = 0.f;
#pragma unroll 8
    for (int e = beg; e < end; e++) {
        int c = g_col[e];
        float w = g_norm_out[c];
        uint2 hv = xs[(size_t)c * 32 + lane];       // 4 halves
        float2 f0 = __half22float2(*(__half2*)&hv.x);
        float2 f1 = __half22float2(*(__half2*)&hv.y);
        ax = fmaf(w, f0.x, ax);
        ay = fmaf(w, f0.y, ay);
        az = fmaf(w, f1.x, az);
        aw = fmaf(w, f1.y, aw);
    }
    float ni = g_norm_in[node];
    float4 o = { ax * ni, ay * ni, az * ni, aw * ni };
    g_agg[(size_t)node * VDIM + lane] = o;
}

// pack two fp32 into (hi,lo)(hi,lo) tf32 uint4
__device__ __forceinline__ uint4 pack2_tf32(float x, float y) {
    uint32_t hx = cvt_tf32(x);
    uint32_t hy = cvt_tf32(y);
    uint4 p;
    p.x = hx; p.y = cvt_tf32(x - __uint_as_float(hx));
    p.z = hy; p.w = cvt_tf32(y - __uint_as_float(hy));
    return p;
}

// ---------------- tf32 mma GEMM + bias + LN + leaky (+ W3 projection) -----------------
#define AP2 20     // A pitch in uint2
#define BP2 132    // B pitch in uint2
template <int MODE, int WSEL>
__global__ __launch_bounds__(256)
void gemm_mma_kernel(const float* __restrict__ b,
                     const float* __restrict__ g, const float* __restrict__ be,
                     const float* __restrict__ W3) {
    __shared__ uint2 As[128][AP2];                 // 20 KB   (k index 0..15)
    __shared__ uint2 Bs[16][BP2];                  // 16.9 KB (col 0..127)
    __shared__ float sh_b[128], sh_g[128], sh_be[128], sh_w3[256];
    __shared__ float sh_s0[128][2], sh_s1[128][2];

    const uint2* __restrict__ W2 = (WSEL == 0) ? g_w2a : g_w2b;

    int tid = threadIdx.x;
    int wid = tid >> 5, lane = tid & 31;
    int lg = lane >> 2, lt = lane & 3;
    int warp_m = wid & 3, warp_n = wid >> 2;
    int mbase = warp_m * 32, nbase = warp_n * 64;
    int rowBase = blockIdx.x * 128;

    if (tid < 128) { sh_b[tid] = b[tid]; sh_g[tid] = g[tid]; sh_be[tid] = be[tid]; }
    if (MODE == 1 && tid >= 128) {
        sh_w3[2 * (tid - 128)] = W3[2 * (tid - 128)];
        sh_w3[2 * (tid - 128) + 1] = W3[2 * (tid - 128) + 1];
    }

    float acc[2][8][4];
#pragma unroll
    for (int m = 0; m < 2; m++)
#pragma unroll
        for (int n = 0; n < 8; n++)
#pragma unroll
            for (int e = 0; e < 4; e++) acc[m][n][e] = 0.f;

    const float* Af = (const float*)g_agg;
    int a_row = tid >> 1;                 // staging: 2 threads per A row
    int a_half = tid & 1;                 // k-half (8 elems)
    int b_k = tid >> 4;                   // staging: 16 threads per B row
    int b_j = tid & 15;                   // uint4 group

    for (int kc = 0; kc < 8; kc++) {
        {
            int gr = rowBase + a_row;
            float4 v0 = make_float4(0.f, 0.f, 0.f, 0.f), v1 = v0;
            if (gr < N_NODES) {
                const float* p = Af + (size_t)gr * DIM + kc * 16 + a_half * 8;
                v0 = *(const float4*)p;
                v1 = *(const float4*)(p + 4);
            }
            uint4* dst = (uint4*)&As[a_row][a_half * 8];
            dst[0] = pack2_tf32(v0.x, v0.y);
            dst[1] = pack2_tf32(v0.z, v0.w);
            dst[2] = pack2_tf32(v1.x, v1.y);
            dst[3] = pack2_tf32(v1.z, v1.w);
        }
        {
            const uint4* srcw = (const uint4*)(W2 + (size_t)(kc * 16 + b_k) * 128);
            uint4* dstw = (uint4*)&Bs[b_k][0];
#pragma unroll
            for (int r = 0; r < 4; r++) dstw[b_j + r * 16] = srcw[b_j + r * 16];
        }
        __syncthreads();

#pragma unroll
        for (int ks = 0; ks < 2; ks++) {
            int kb = ks * 8;
            uint32_t a_hi[2][4], a_lo[2][4];
#pragma unroll
            for (int m = 0; m < 2; m++) {
                int r0 = mbase + m * 16 + lg;
                uint2 p0 = As[r0][kb + lt];
                uint2 p1 = As[r0 + 8][kb + lt];
                uint2 p2 = As[r0][kb + lt + 4];
                uint2 p3 = As[r0 + 8][kb + lt + 4];
                a_hi[m][0] = p0.x; a_lo[m][0] = p0.y;
                a_hi[m][1] = p1.x; a_lo[m][1] = p1.y;
                a_hi[m][2] = p2.x; a_lo[m][2] = p2.y;
                a_hi[m][3] = p3.x; a_lo[m][3] = p3.y;
            }
#pragma unroll
            for (int n = 0; n < 8; n++) {
                int c0 = nbase + n * 8 + lg;
                uint2 q0 = Bs[kb + lt][c0];
                uint2 q1 = Bs[kb + lt + 4][c0];
#pragma unroll
                for (int m = 0; m < 2; m++) {
                    mma8(acc[m][n], a_hi[m], q0.x, q1.x);   // hi*hi
                    mma8(acc[m][n], a_hi[m], q0.y, q1.y);   // hi*lo
                    mma8(acc[m][n], a_lo[m], q0.x, q1.x);   // lo*hi
                }
            }
        }
        __syncthreads();
    }

    // ---- epilogue: bias, LN stats via shfl + cross-warp SMEM, leaky, output ----
#pragma unroll
    for (int m = 0; m < 2; m++)
#pragma unroll
        for (int n = 0; n < 8; n++) {
            int col = nbase + n * 8 + 2 * lt;
            acc[m][n][0] += sh_b[col];
            acc[m][n][1] += sh_b[col + 1];
            acc[m][n][2] += sh_b[col];
            acc[m][n][3] += sh_b[col + 1];
        }

    float rs[2][2];
#pragma unroll
    for (int m = 0; m < 2; m++) {
        float s0 = 0.f, s1 = 0.f;
#pragma unroll
        for (int n = 0; n < 8; n++) {
            s0 += acc[m][n][0] + acc[m][n][1];
            s1 += acc[m][n][2] + acc[m][n][3];
        }
        rs[m][0] = s0; rs[m][1] = s1;
    }
#pragma unroll
    for (int o = 1; o <= 2; o <<= 1) {
#pragma unroll
        for (int m = 0; m < 2; m++) {
            rs[m][0] += __shfl_xor_sync(0xffffffffu, rs[m][0], o);
            rs[m][1] += __shfl_xor_sync(0xffffffffu, rs[m][1], o);
        }
    }
    if (lt == 0) {
#pragma unroll
        for (int m = 0; m < 2; m++) {
            sh_s0[mbase + m * 16 + lg][warp_n] = rs[m][0];
            sh_s0[mbase + m * 16 + lg + 8][warp_n] = rs[m][1];
        }
    }
    __syncthreads();

    float mu[2][2];
#pragma unroll
    for (int m = 0; m < 2; m++) {
        int r0 = mbase + m * 16 + lg;
        mu[m][0] = (sh_s0[r0][0] + sh_s0[r0][1]) * (1.f / DIM);
        mu[m][1] = (sh_s0[r0 + 8][0] + sh_s0[r0 + 8][1]) * (1.f / DIM);
    }

    float qs[2][2];
#pragma unroll
    for (int m = 0; m < 2; m++) {
        float q0 = 0.f, q1 = 0.f;
#pragma unroll
        for (int n = 0; n < 8; n++) {
            float d;
            d = acc[m][n][0] - mu[m][0]; q0 += d * d;
            d = acc[m][n][1] - mu[m][0]; q0 += d * d;
            d = acc[m][n][2] - mu[m][1]; q1 += d * d;
            d = acc[m][n][3] - mu[m][1]; q1 += d * d;
        }
        qs[m][0] = q0; qs[m][1] = q1;
    }
#pragma unroll
    for (int o = 1; o <= 2; o <<= 1) {
#pragma unroll
        for (int m = 0; m < 2; m++) {
            qs[m][0] += __shfl_xor_sync(0xffffffffu, qs[m][0], o);
            qs[m][1] += __shfl_xor_sync(0xffffffffu, qs[m][1], o);
        }
    }
    if (lt == 0) {
#pragma unroll
        for (int m = 0; m < 2; m++) {
            sh_s1[mbase + m * 16 + lg][warp_n] = qs[m][0];
            sh_s1[mbase + m * 16 + lg + 8][warp_n] = qs[m][1];
        }
    }
    __syncthreads();

    float rstd[2][2];
#pragma unroll
    for (int m = 0; m < 2; m++) {
        int r0 = mbase + m * 16 + lg;
        rstd[m][0] = rsqrtf((sh_s1[r0][0] + sh_s1[r0][1]) * (1.f / DIM) + LN_EPS);
        rstd[m][1] = rsqrtf((sh_s1[r0 + 8][0] + sh_s1[r0 + 8][1]) * (1.f / DIM) + LN_EPS);
    }

    if (MODE == 0) {
        __half* xh = (__half*)g_xh;
#pragma unroll
        for (int m = 0; m < 2; m++) {
            int r0 = mbase + m * 16 + lg;
#pragma unroll
            for (int h = 0; h < 2; h++) {
                int gr = rowBase + r0 + h * 8;
                if (gr < N_NODES) {
#pragma unroll
                    for (int n = 0; n < 8; n++) {
                        int col = nbase + n * 8 + 2 * lt;
                        float v0 = (acc[m][n][h * 2 + 0] - mu[m][h]) * rstd[m][h] * sh_g[col] + sh_be[col];
                        float v1 = (acc[m][n][h * 2 + 1] - mu[m][h]) * rstd[m][h] * sh_g[col + 1] + sh_be[col + 1];
                        v0 = v0 > 0.f ? v0 : LEAKY * v0;
                        v1 = v1 > 0.f ? v1 : LEAKY * v1;
                        __half2 hp = __floats2half2_rn(v0, v1);
                        *(__half2*)(xh + (size_t)gr * DIM + col) = hp;
                    }
                }
            }
        }
    } else {
        __syncthreads();   // reuse sh_s0/sh_s1
        float p0[2][2], p1[2][2];
#pragma unroll
        for (int m = 0; m < 2; m++)
#pragma unroll
            for (int h = 0; h < 2; h++) { p0[m][h] = 0.f; p1[m][h] = 0.f; }
#pragma unroll
        for (int m = 0; m < 2; m++)
#pragma unroll
            for (int n = 0; n < 8; n++) {
                int col = nbase + n * 8 + 2 * lt;
#pragma unroll
                for (int h = 0; h < 2; h++) {
                    float v0 = (acc[m][n][h * 2 + 0] - mu[m][h]) * rstd[m][h] * sh_g[col] + sh_be[col];
                    float v1 = (acc[m][n][h * 2 + 1] - mu[m][h]) * rstd[m][h] * sh_g[col + 1] + sh_be[col + 1];
                    v0 = v0 > 0.f ? v0 : LEAKY * v0;
                    v1 = v1 > 0.f ? v1 : LEAKY * v1;
                    p0[m][h] += v0 * sh_w3[col * 2 + 0] + v1 * sh_w3[(col + 1) * 2 + 0];
                    p1[m][h] += v0 * sh_w3[col * 2 + 1] + v1 * sh_w3[(col + 1) * 2 + 1];
                }
            }
#pragma unroll
        for (int o = 1; o <= 2; o <<= 1) {
#pragma unroll
            for (int m = 0; m < 2; m++)
#pragma unroll
                for (int h = 0; h < 2; h++) {
                    p0[m][h] += __shfl_xor_sync(0xffffffffu, p0[m][h], o);
                    p1[m][h] += __shfl_xor_sync(0xffffffffu, p1[m][h], o);
                }
        }
        if (lt == 0) {
#pragma unroll
            for (int m = 0; m < 2; m++)
#pragma unroll
                for (int h = 0; h < 2; h++) {
                    sh_s0[mbase + m * 16 + lg + h * 8][warp_n] = p0[m][h];
                    sh_s1[mbase + m * 16 + lg + h * 8][warp_n] = p1[m][h];
                }
        }
        __syncthreads();
        if (tid < 128) {
            int gr = rowBase + tid;
            if (gr < N_NODES) {
                float no = g_norm_out[gr];
                float2 p = { no * (sh_s0[tid][0] + sh_s0[tid][1]),
                             no * (sh_s1[tid][0] + sh_s1[tid][1]) };
                g_proj[gr] = p;
            }
        }
    }
}

// ---------------- final aggregation over 2-dim projected features ----------------
__global__ void agg2_kernel(const float* __restrict__ b3, float* __restrict__ out) {
    int node = blockIdx.x * blockDim.x + threadIdx.x;
    if (node >= N_NODES) return;
    int beg = g_beg[node];
    int end = beg + g_deg_in[node];
    float a0 = 0.f, a1 = 0.f;
#pragma unroll 4
    for (int e = beg; e < end; e++) {
        float2 p = g_proj[g_col[e]];
        a0 += p.x;
        a1 += p.y;
    }
    float ni = g_norm_in[node];
    out[node * 2 + 0] = ni * a0 + b3[0];
    out[node * 2 + 1] = ni * a1 + b3[1];
}

// ---------------- launch: 9 kernels, no host refs to device symbols ----------------
extern "C" void kernel_launch(void* const* d_in, const int* in_sizes, int n_in,
                              void* d_out, int out_size) {
    const float* feat = (const float*)d_in[0];
    const int*   src  = (const int*)d_in[1];   // int32 (JAX x64 disabled)
    const int*   dst  = (const int*)d_in[2];
    const float* W1  = (const float*)d_in[3];
    const float* b1  = (const float*)d_in[4];
    const float* W2  = (const float*)d_in[5];
    const float* b2  = (const float*)d_in[6];
    const float* W3  = (const float*)d_in[7];
    const float* b3  = (const float*)d_in[8];
    const float* g1  = (const float*)d_in[9];
    const float* be1 = (const float*)d_in[10];
    const float* g2  = (const float*)d_in[11];
    const float* be2 = (const float*)d_in[12];
    float* out = (float*)d_out;

    const int NB_N  = (N_NODES + 255) / 256;
    const int NB_E8 = (N_EDGES / 8 + 255) / 256;
    const int NB_E4 = (N_EDGES / 4 + 255) / 256;
    const int NB_W  = (N_NODES + 7) / 8;
    const int NB_G  = (N_NODES + 127) / 128;   // 391
    const int NB_I  = (N_NODES * 16 + 255) / 256;

    // prologue: 4 launches (was 7)
    init_kernel<<<NB_I, 256>>>((const float4*)feat);
    count_deg_kernel<<<NB_E8, 256>>>((const int4*)src, (const int4*)dst);
    alloc_split_kernel<<<N_SBLK + 128, 256>>>(W1, W2);
    fill_csr_kernel<<<NB_E4, 256>>>((const int4*)src, (const int4*)dst);

    // layer 1
    agg128_kernel<false><<<NB_W, 256>>>();
    gemm_mma_kernel<0, 0><<<NB_G, 256>>>(b1, g1, be1, nullptr);

    // layer 2 (+ fused W3 projection)
    agg128_kernel<true><<<NB_W, 256>>>();
    gemm_mma_kernel<1, 1><<<NB_G, 256>>>(b2, g2, be2, W3);

    // layer 3 aggregation
    agg2_kernel<<<NB_N, 256>>>(b3, out);
}